// round 7
// baseline (speedup 1.0000x reference)
#include <cuda_runtime.h>
#include <cuda_bf16.h>
#include <math_constants.h>

// Problem constants (fixed by setup_inputs)
#define Bq 4
#define Hq 8
#define BH 32          // B*H
#define Lq 2048
#define Dq 64
#define SK 40          // sample_k
#define NT 40          // n_top
#define SCALE 0.125f   // 1/sqrt(64)

// ---------------- scratch (device globals; no allocation) ----------------
__device__ float g_M[BH * Lq];                 // 256 KB
__device__ int   g_top[BH * NT];               // 5 KB
__device__ float g_vmean[BH * Dq];             // 8 KB
__device__ float g_mrow[BH * NT];              // per-row softmax max
__device__ float g_inv[BH * NT];               // per-row 1/softmax_sum
__device__ float g_scores[(size_t)BH * NT * Lq];   // 10.5 MB (raw scaled scores)
__device__ float g_part[8 * BH * NT * Dq];     // 2.6 MB (k-split partials)

// ---------------- kernel 1: M[bh,l] = max_s q.k - sum_s/L ----------------
// Warp per query; transpose-fold reductions (V-1 shuffles for V arrays).
template<int O, int V>
__device__ __forceinline__ void fold(float* p, int lane) {
    bool hi = (lane & O) != 0;
    #pragma unroll
    for (int j = 0; j < V / 2; j++) {
        float send = hi ? p[j] : p[j + V / 2];
        float keep = hi ? p[j + V / 2] : p[j];
        p[j] = keep + __shfl_xor_sync(0xffffffffu, send, O);
    }
}

__device__ __forceinline__ float dot16(const float* __restrict__ Kb, float2 q,
                                       int e, int base, int lane) {
    float p[16];
    #pragma unroll
    for (int j = 0; j < 16; j++) {
        int idx = __shfl_sync(0xffffffffu, e, base + j);
        float2 k = ((const float2*)(Kb + (size_t)idx * Dq))[lane];
        p[j] = q.x * k.x + q.y * k.y;
    }
    fold<16, 16>(p, lane);
    fold<8, 8>(p, lane);
    fold<4, 4>(p, lane);
    fold<2, 2>(p, lane);
    p[0] += __shfl_xor_sync(0xffffffffu, p[0], 1);
    return p[0];
}

__device__ __forceinline__ float dot8(const float* __restrict__ Kb, float2 q,
                                      int e, int lane) {
    float p[8];
    #pragma unroll
    for (int j = 0; j < 8; j++) {
        int idx = __shfl_sync(0xffffffffu, e, j);
        float2 k = ((const float2*)(Kb + (size_t)idx * Dq))[lane];
        p[j] = q.x * k.x + q.y * k.y;
    }
    fold<16, 8>(p, lane);
    fold<8, 4>(p, lane);
    fold<4, 2>(p, lane);
    p[0] += __shfl_xor_sync(0xffffffffu, p[0], 2);
    p[0] += __shfl_xor_sync(0xffffffffu, p[0], 1);
    return p[0];
}

__global__ void k_M(const float* __restrict__ Q, const float* __restrict__ K,
                    const int* __restrict__ idxs) {
    int w = blockIdx.x * 8 + (threadIdx.x >> 5);   // query id (bh*2048 + l)
    int lane = threadIdx.x & 31;
    int bh = w >> 11;
    int l  = w & (Lq - 1);
    float2 q = ((const float2*)(Q + (size_t)w * Dq))[lane];
    const float* Kb = K + (size_t)bh * Lq * Dq;
    int e0 = idxs[l * SK + lane];
    int e1 = (lane < 8) ? idxs[l * SK + 32 + lane] : 0;

    float a = dot16(Kb, q, e0, 0, lane);
    float b = dot16(Kb, q, e0, 16, lane);
    float c = dot8(Kb, q, e1, lane);

    float mx = fmaxf(fmaxf(a, b), c);
    float sm = 0.5f * (a + b) + 0.25f * c;
    #pragma unroll
    for (int o = 16; o; o >>= 1) {
        mx = fmaxf(mx, __shfl_xor_sync(0xffffffffu, mx, o));
        sm += __shfl_xor_sync(0xffffffffu, sm, o);
    }
    if (lane == 0) g_M[w] = mx - sm * (1.0f / (float)Lq);
}

// ---------------- kernel 2: top-40 per (b,h), radix-bin select -----------
__global__ void k_topk() {
    __shared__ unsigned keys[Lq];
    __shared__ int hist[256];
    __shared__ unsigned red_k[8];
    __shared__ int red_i[8];
    __shared__ int s_T, s_need, s_cnt;
    int bh = blockIdx.x;
    int t = threadIdx.x;
    hist[t] = 0;
    __syncthreads();
    for (int i = t; i < Lq; i += 256) {
        unsigned u = __float_as_uint(g_M[bh * Lq + i]);
        unsigned k = (u & 0x80000000u) ? ~u : (u | 0x80000000u);
        keys[i] = k;
        atomicAdd(&hist[k >> 24], 1);
    }
    __syncthreads();
    if (t == 0) {
        int acc = 0, T = 0;
        for (int b = 255; b >= 0; b--) {
            if (acc + hist[b] >= NT) { T = b; break; }
            acc += hist[b];
        }
        s_T = T; s_need = NT - acc; s_cnt = 0;
    }
    __syncthreads();
    int T = s_T, need = s_need;
    for (int i = t; i < Lq; i += 256) {
        if ((int)(keys[i] >> 24) > T) {
            int p = atomicAdd(&s_cnt, 1);
            g_top[bh * NT + p] = i;
        }
    }
    __syncthreads();
    int lane = t & 31, wid = t >> 5;
    for (int it = 0; it < need; it++) {
        unsigned bk = 0; int bi = Lq;
        for (int i = t; i < Lq; i += 256) {
            unsigned k = keys[i];
            if ((int)(k >> 24) == T && (k > bk || (k == bk && i < bi))) { bk = k; bi = i; }
        }
        #pragma unroll
        for (int o = 16; o; o >>= 1) {
            unsigned ok = __shfl_xor_sync(0xffffffffu, bk, o);
            int oi = __shfl_xor_sync(0xffffffffu, bi, o);
            if (ok > bk || (ok == bk && oi < bi)) { bk = ok; bi = oi; }
        }
        if (lane == 0) { red_k[wid] = bk; red_i[wid] = bi; }
        __syncthreads();
        if (t == 0) {
            for (int wN = 1; wN < 8; wN++)
                if (red_k[wN] > bk || (red_k[wN] == bk && red_i[wN] < bi)) { bk = red_k[wN]; bi = red_i[wN]; }
            g_top[bh * NT + (NT - need) + it] = bi;
            keys[bi] = 0;
        }
        __syncthreads();
    }
}

// ---------------- kernel 3: V mean over L per (b,h), float4 --------------
__global__ void k_vmean(const float* __restrict__ V) {
    __shared__ float4 ps[256];
    int bh = blockIdx.x;
    int t = threadIdx.x;               // 256
    int d4 = t & 15, part = t >> 4;    // 16 parts x 128 rows
    const float4* Vb = (const float4*)(V + (size_t)bh * Lq * Dq);
    float4 s = make_float4(0.f, 0.f, 0.f, 0.f);
    int k0 = part * 128;
    for (int k = k0; k < k0 + 128; k++) {
        float4 v = Vb[(size_t)k * 16 + d4];
        s.x += v.x; s.y += v.y; s.z += v.z; s.w += v.w;
    }
    ps[t] = s;
    __syncthreads();
    if (t < 16) {
        float4 a = ps[t];
        #pragma unroll
        for (int pI = 1; pI < 16; pI++) {
            float4 v = ps[pI * 16 + t];
            a.x += v.x; a.y += v.y; a.z += v.z; a.w += v.w;
        }
        const float inv = 1.0f / (float)Lq;
        a.x *= inv; a.y *= inv; a.z *= inv; a.w *= inv;
        ((float4*)g_vmean)[bh * 16 + t] = a;
    }
}

// ---------------- kernel 4: broadcast V_mean (wide grid) -----------------
__global__ void k_fill(float4* __restrict__ out4) {
    int i = blockIdx.x * 256 + threadIdx.x;  // BH*L*16 float4s
    int bh = i >> 15;
    int d4 = i & 15;
    out4[i] = ((const float4*)g_vmean)[bh * 16 + d4];
}

// ---------------- kernel 5: scores_top = (Q_top @ K^T) * scale -----------
// 64-key tiles -> grid BH*32 = 1024 blocks (2x warp parallelism vs 128-key).
__global__ void k_scores(const float* __restrict__ Q, const float* __restrict__ K) {
    __shared__ float qs[NT * Dq];           // 40x64 = 10 KB
    __shared__ float Kt[Dq * 68];           // transposed [d][k], pad 68
    int bh = blockIdx.x >> 5;
    int kt = blockIdx.x & 31;
    int t = threadIdx.x;
    const float* Qb = Q + (size_t)bh * Lq * Dq;
    const float* Kb = K + (size_t)bh * Lq * Dq;
    for (int j = t; j < NT * Dq; j += 256) {
        int u = j >> 6, d = j & 63;
        int qi = __ldg(&g_top[bh * NT + u]);
        qs[j] = Qb[(size_t)qi * Dq + d];
    }
    for (int j = t; j < 64 * Dq; j += 256) {
        int r = j >> 6, d = j & 63;
        Kt[d * 68 + r] = Kb[(size_t)(kt * 64 + r) * Dq + d];
    }
    __syncthreads();
    int tu = t >> 5;          // 8 warps x 5 queries
    int tk = t & 31;          // 2 keys each
    float acc[5][2] = {};
    #pragma unroll 8
    for (int d = 0; d < Dq; d++) {
        float a[5];
        #pragma unroll
        for (int i = 0; i < 5; i++) a[i] = qs[(tu * 5 + i) * Dq + d];
        float2 b = *(const float2*)&Kt[d * 68 + tk * 2];
        #pragma unroll
        for (int i = 0; i < 5; i++) {
            acc[i][0] = fmaf(a[i], b.x, acc[i][0]);
            acc[i][1] = fmaf(a[i], b.y, acc[i][1]);
        }
    }
    #pragma unroll
    for (int i = 0; i < 5; i++) {
        int u = tu * 5 + i;
        float2 r;
        r.x = acc[i][0] * SCALE; r.y = acc[i][1] * SCALE;
        *(float2*)&g_scores[((size_t)(bh * NT + u)) * Lq + kt * 64 + tk * 2] = r;
    }
}

// ---------------- kernel 6: softmax stats only (max + 1/sum, no write) ---
__global__ void k_softmax() {
    __shared__ float red[8];
    int row = blockIdx.x;                  // BH*NT = 1280 rows
    const float* s = g_scores + (size_t)row * Lq;
    int t = threadIdx.x, lane = t & 31, wid = t >> 5;
    float mx = -CUDART_INF_F;
    for (int i = t; i < Lq; i += 256) mx = fmaxf(mx, s[i]);
    #pragma unroll
    for (int o = 16; o; o >>= 1) mx = fmaxf(mx, __shfl_xor_sync(0xffffffffu, mx, o));
    if (lane == 0) red[wid] = mx;
    __syncthreads();
    mx = red[0];
    #pragma unroll
    for (int i = 1; i < 8; i++) mx = fmaxf(mx, red[i]);
    __syncthreads();
    float sum = 0.f;
    for (int i = t; i < Lq; i += 256) sum += __expf(s[i] - mx);
    #pragma unroll
    for (int o = 16; o; o >>= 1) sum += __shfl_xor_sync(0xffffffffu, sum, o);
    if (lane == 0) red[wid] = sum;
    __syncthreads();
    if (t == 0) {
        sum = 0.f;
        #pragma unroll
        for (int i = 0; i < 8; i++) sum += red[i];
        g_mrow[row] = mx;
        g_inv[row] = 1.0f / sum;
    }
}

// ---------------- kernel 7: ctx partial = exp(scores-m) @ V (k-split) ----
__global__ void k_ctx(const float* __restrict__ V) {
    __shared__ float Vs[128 * Dq];          // 32 KB
    int bh = blockIdx.x >> 3;
    int ks = blockIdx.x & 7;
    int t = threadIdx.x;
    int tu = t >> 5;
    int td = t & 31;
    const float* Vb = V + (size_t)bh * Lq * Dq;
    const float* Sb = g_scores + (size_t)bh * NT * Lq;
    float m[5];
    #pragma unroll
    for (int i = 0; i < 5; i++) m[i] = g_mrow[bh * NT + tu * 5 + i];
    float acc[5][2] = {};
    for (int sub = 0; sub < 2; sub++) {
        int k0 = ks * 256 + sub * 128;
        __syncthreads();
        for (int j = t; j < 128 * Dq; j += 256) Vs[j] = Vb[(size_t)k0 * Dq + j];
        __syncthreads();
        #pragma unroll 4
        for (int kk = 0; kk < 128; kk++) {
            float a[5];
            #pragma unroll
            for (int i = 0; i < 5; i++)
                a[i] = __expf(__ldg(&Sb[(size_t)(tu * 5 + i) * Lq + k0 + kk]) - m[i]);
            float2 v = *(const float2*)&Vs[kk * Dq + td * 2];
            #pragma unroll
            for (int i = 0; i < 5; i++) {
                acc[i][0] = fmaf(a[i], v.x, acc[i][0]);
                acc[i][1] = fmaf(a[i], v.y, acc[i][1]);
            }
        }
    }
    #pragma unroll
    for (int i = 0; i < 5; i++) {
        int u = tu * 5 + i;
        float2 r; r.x = acc[i][0]; r.y = acc[i][1];
        *(float2*)&g_part[(((size_t)ks * BH + bh) * NT + u) * Dq + td * 2] = r;
    }
}

// ---------------- kernel 8: sum partials * inv_sum, scatter --------------
__global__ void k_scatter(float* __restrict__ out) {
    int i = blockIdx.x * blockDim.x + threadIdx.x;   // BH*NT*D = 81920
    if (i >= BH * NT * Dq) return;
    int d = i & 63;
    int u = (i >> 6) % NT;
    int bh = (i >> 6) / NT;
    float s = 0.f;
    #pragma unroll
    for (int ks = 0; ks < 8; ks++)
        s += g_part[(((size_t)ks * BH + bh) * NT + u) * Dq + d];
    s *= g_inv[bh * NT + u];
    int qi = g_top[bh * NT + u];
    out[((size_t)bh * Lq + qi) * Dq + d] = s;
}

// ---------------- launch ---------------------------------------------------
extern "C" void kernel_launch(void* const* d_in, const int* in_sizes, int n_in,
                              void* d_out, int out_size) {
    const float* Q = (const float*)d_in[0];
    const float* K = (const float*)d_in[1];
    const float* V = (const float*)d_in[2];
    const int* idxs = (const int*)d_in[3];
    float* out = (float*)d_out;

    // order: k_scores is user launch #4 (profiled) to verify the widening.
    k_vmean<<<BH, 256>>>(V);                             // 1
    k_M<<<(BH * Lq) / 8, 256>>>(Q, K, idxs);             // 2
    k_topk<<<BH, 256>>>();                               // 3
    k_scores<<<BH * 32, 256>>>(Q, K);                    // 4  <-- profiled
    k_fill<<<(BH * Lq * Dq / 4) / 256, 256>>>((float4*)out); // 5
    k_softmax<<<BH * NT, 256>>>();                       // 6
    k_ctx<<<BH * 8, 256>>>(V);                           // 7
    k_scatter<<<(BH * NT * Dq + 255) / 256, 256>>>(out); // 8
}

// round 8
// speedup vs baseline: 1.1576x; 1.1576x over previous
#include <cuda_runtime.h>
#include <cuda_bf16.h>
#include <math_constants.h>

// Problem constants (fixed by setup_inputs)
#define Bq 4
#define Hq 8
#define BH 32          // B*H
#define Lq 2048
#define Dq 64
#define SK 40          // sample_k
#define NT 40          // n_top
#define SCALE 0.125f   // 1/sqrt(64)

// ---------------- scratch (device globals; no allocation) ----------------
__device__ float g_M[BH * Lq];                 // 256 KB
__device__ int   g_top[BH * NT];               // 5 KB
__device__ float g_vmean[BH * Dq];             // 8 KB
__device__ float g_inv[BH * NT];               // per-row 1/softmax_sum
__device__ float g_scores[(size_t)BH * NT * Lq];   // 10.5 MB
__device__ float g_part[8 * BH * NT * Dq];     // 2.6 MB (k-split partials)

// ---------------- kernel 1: M[bh,l] = max_s q.k - sum_s/L ----------------
template<int O, int V>
__device__ __forceinline__ void fold(float* p, int lane) {
    bool hi = (lane & O) != 0;
    #pragma unroll
    for (int j = 0; j < V / 2; j++) {
        float send = hi ? p[j] : p[j + V / 2];
        float keep = hi ? p[j + V / 2] : p[j];
        p[j] = keep + __shfl_xor_sync(0xffffffffu, send, O);
    }
}

__device__ __forceinline__ float dot16(const float* __restrict__ Kb, float2 q,
                                       int e, int base, int lane) {
    float p[16];
    #pragma unroll
    for (int j = 0; j < 16; j++) {
        int idx = __shfl_sync(0xffffffffu, e, base + j);
        float2 k = ((const float2*)(Kb + (size_t)idx * Dq))[lane];
        p[j] = q.x * k.x + q.y * k.y;
    }
    fold<16, 16>(p, lane);
    fold<8, 8>(p, lane);
    fold<4, 4>(p, lane);
    fold<2, 2>(p, lane);
    p[0] += __shfl_xor_sync(0xffffffffu, p[0], 1);
    return p[0];
}

__device__ __forceinline__ float dot8(const float* __restrict__ Kb, float2 q,
                                      int e, int lane) {
    float p[8];
    #pragma unroll
    for (int j = 0; j < 8; j++) {
        int idx = __shfl_sync(0xffffffffu, e, j);
        float2 k = ((const float2*)(Kb + (size_t)idx * Dq))[lane];
        p[j] = q.x * k.x + q.y * k.y;
    }
    fold<16, 8>(p, lane);
    fold<8, 4>(p, lane);
    fold<4, 2>(p, lane);
    p[0] += __shfl_xor_sync(0xffffffffu, p[0], 2);
    p[0] += __shfl_xor_sync(0xffffffffu, p[0], 1);
    return p[0];
}

__global__ void k_M(const float* __restrict__ Q, const float* __restrict__ K,
                    const int* __restrict__ idxs) {
    int w = blockIdx.x * 8 + (threadIdx.x >> 5);   // query id (bh*2048 + l)
    int lane = threadIdx.x & 31;
    int bh = w >> 11;
    int l  = w & (Lq - 1);
    float2 q = ((const float2*)(Q + (size_t)w * Dq))[lane];
    const float* Kb = K + (size_t)bh * Lq * Dq;
    int e0 = idxs[l * SK + lane];
    int e1 = (lane < 8) ? idxs[l * SK + 32 + lane] : 0;

    float a = dot16(Kb, q, e0, 0, lane);
    float b = dot16(Kb, q, e0, 16, lane);
    float c = dot8(Kb, q, e1, lane);

    float mx = fmaxf(fmaxf(a, b), c);
    float sm = 0.5f * (a + b) + 0.25f * c;
    #pragma unroll
    for (int o = 16; o; o >>= 1) {
        mx = fmaxf(mx, __shfl_xor_sync(0xffffffffu, mx, o));
        sm += __shfl_xor_sync(0xffffffffu, sm, o);
    }
    if (lane == 0) g_M[w] = mx - sm * (1.0f / (float)Lq);
}

// ---------------- kernel 2: top-40 per (b,h), radix-bin select -----------
__global__ void k_topk() {
    __shared__ unsigned keys[Lq];
    __shared__ int hist[256];
    __shared__ unsigned red_k[8];
    __shared__ int red_i[8];
    __shared__ int s_T, s_need, s_cnt;
    int bh = blockIdx.x;
    int t = threadIdx.x;
    hist[t] = 0;
    __syncthreads();
    for (int i = t; i < Lq; i += 256) {
        unsigned u = __float_as_uint(g_M[bh * Lq + i]);
        unsigned k = (u & 0x80000000u) ? ~u : (u | 0x80000000u);
        keys[i] = k;
        atomicAdd(&hist[k >> 24], 1);
    }
    __syncthreads();
    if (t == 0) {
        int acc = 0, T = 0;
        for (int b = 255; b >= 0; b--) {
            if (acc + hist[b] >= NT) { T = b; break; }
            acc += hist[b];
        }
        s_T = T; s_need = NT - acc; s_cnt = 0;
    }
    __syncthreads();
    int T = s_T, need = s_need;
    for (int i = t; i < Lq; i += 256) {
        if ((int)(keys[i] >> 24) > T) {
            int p = atomicAdd(&s_cnt, 1);
            g_top[bh * NT + p] = i;
        }
    }
    __syncthreads();
    int lane = t & 31, wid = t >> 5;
    for (int it = 0; it < need; it++) {
        unsigned bk = 0; int bi = Lq;
        for (int i = t; i < Lq; i += 256) {
            unsigned k = keys[i];
            if ((int)(k >> 24) == T && (k > bk || (k == bk && i < bi))) { bk = k; bi = i; }
        }
        #pragma unroll
        for (int o = 16; o; o >>= 1) {
            unsigned ok = __shfl_xor_sync(0xffffffffu, bk, o);
            int oi = __shfl_xor_sync(0xffffffffu, bi, o);
            if (ok > bk || (ok == bk && oi < bi)) { bk = ok; bi = oi; }
        }
        if (lane == 0) { red_k[wid] = bk; red_i[wid] = bi; }
        __syncthreads();
        if (t == 0) {
            for (int wN = 1; wN < 8; wN++)
                if (red_k[wN] > bk || (red_k[wN] == bk && red_i[wN] < bi)) { bk = red_k[wN]; bi = red_i[wN]; }
            g_top[bh * NT + (NT - need) + it] = bi;
            keys[bi] = 0;
        }
        __syncthreads();
    }
}

// ---------------- kernel 3: V mean over L per (b,h), float4 --------------
__global__ void k_vmean(const float* __restrict__ V) {
    __shared__ float4 ps[256];
    int bh = blockIdx.x;
    int t = threadIdx.x;               // 256
    int d4 = t & 15, part = t >> 4;    // 16 parts x 128 rows
    const float4* Vb = (const float4*)(V + (size_t)bh * Lq * Dq);
    float4 s = make_float4(0.f, 0.f, 0.f, 0.f);
    int k0 = part * 128;
    for (int k = k0; k < k0 + 128; k++) {
        float4 v = Vb[(size_t)k * 16 + d4];
        s.x += v.x; s.y += v.y; s.z += v.z; s.w += v.w;
    }
    ps[t] = s;
    __syncthreads();
    if (t < 16) {
        float4 a = ps[t];
        #pragma unroll
        for (int pI = 1; pI < 16; pI++) {
            float4 v = ps[pI * 16 + t];
            a.x += v.x; a.y += v.y; a.z += v.z; a.w += v.w;
        }
        const float inv = 1.0f / (float)Lq;
        a.x *= inv; a.y *= inv; a.z *= inv; a.w *= inv;
        ((float4*)g_vmean)[bh * 16 + t] = a;
    }
}

// ---------------- kernel 4: broadcast V_mean (wide grid) -----------------
__global__ void k_fill(float4* __restrict__ out4) {
    int i = blockIdx.x * 256 + threadIdx.x;  // BH*L*16 float4s
    int bh = i >> 15;
    int d4 = i & 15;
    out4[i] = ((const float4*)g_vmean)[bh * 16 + d4];
}

// ---------------- kernel 5: scores = (Q_top @ K^T) * scale ---------------
// 128-key tile, 512 threads (16 warps): warp wq handles queries wq/2*5..+5,
// key half (wq&1)*64. grid BH*16 = 512 blocks, 8192 warps chip-wide.
__global__ void k_scores(const float* __restrict__ Q, const float* __restrict__ K) {
    __shared__ float qs[NT * Dq];           // 10 KB
    __shared__ float Kt[Dq * 132];          // transposed [d][k], pad 132
    int bh = blockIdx.x >> 4;
    int kt = blockIdx.x & 15;
    int t = threadIdx.x;                    // 512
    const float* Qb = Q + (size_t)bh * Lq * Dq;
    const float* Kb = K + (size_t)bh * Lq * Dq;
    for (int j = t; j < NT * Dq; j += 512) {
        int u = j >> 6, d = j & 63;
        int qi = __ldg(&g_top[bh * NT + u]);
        qs[j] = Qb[(size_t)qi * Dq + d];
    }
    for (int j = t; j < 128 * Dq; j += 512) {
        int r = j >> 6, d = j & 63;
        Kt[d * 132 + r] = Kb[(size_t)(kt * 128 + r) * Dq + d];
    }
    __syncthreads();
    int w = t >> 5, lane = t & 31;
    int wq = w >> 1;                        // 8 query groups of 5
    int kh = (w & 1) * 64;                  // key half
    float acc[5][2] = {};
    #pragma unroll 8
    for (int d = 0; d < Dq; d++) {
        float a[5];
        #pragma unroll
        for (int i = 0; i < 5; i++) a[i] = qs[(wq * 5 + i) * Dq + d];
        float2 b = *(const float2*)&Kt[d * 132 + kh + lane * 2];
        #pragma unroll
        for (int i = 0; i < 5; i++) {
            acc[i][0] = fmaf(a[i], b.x, acc[i][0]);
            acc[i][1] = fmaf(a[i], b.y, acc[i][1]);
        }
    }
    #pragma unroll
    for (int i = 0; i < 5; i++) {
        int u = wq * 5 + i;
        float2 r;
        r.x = acc[i][0] * SCALE; r.y = acc[i][1] * SCALE;
        *(float2*)&g_scores[((size_t)(bh * NT + u)) * Lq + kt * 128 + kh + lane * 2] = r;
    }
}

// ---------------- kernel 6: softmax 2-pass (exp write + 1/sum) -----------
__global__ void k_softmax() {
    __shared__ float red[8];
    int row = blockIdx.x;                  // BH*NT = 1280 rows
    float* s = g_scores + (size_t)row * Lq;
    int t = threadIdx.x, lane = t & 31, wid = t >> 5;
    float mx = -CUDART_INF_F;
    for (int i = t; i < Lq; i += 256) mx = fmaxf(mx, s[i]);
    #pragma unroll
    for (int o = 16; o; o >>= 1) mx = fmaxf(mx, __shfl_xor_sync(0xffffffffu, mx, o));
    if (lane == 0) red[wid] = mx;
    __syncthreads();
    mx = red[0];
    #pragma unroll
    for (int i = 1; i < 8; i++) mx = fmaxf(mx, red[i]);
    __syncthreads();
    float sum = 0.f;
    for (int i = t; i < Lq; i += 256) {
        float e = __expf(s[i] - mx);
        s[i] = e;
        sum += e;
    }
    #pragma unroll
    for (int o = 16; o; o >>= 1) sum += __shfl_xor_sync(0xffffffffu, sum, o);
    if (lane == 0) red[wid] = sum;
    __syncthreads();
    if (t == 0) {
        sum = 0.f;
        #pragma unroll
        for (int i = 0; i < 8; i++) sum += red[i];
        g_inv[row] = 1.0f / sum;
    }
}

// ---------------- kernel 7: ctx partial = exp_scores @ V (k-split) -------
__global__ void k_ctx(const float* __restrict__ V) {
    __shared__ float Vs[128 * Dq];          // 32 KB
    int bh = blockIdx.x >> 3;
    int ks = blockIdx.x & 7;
    int t = threadIdx.x;
    int tu = t >> 5;
    int td = t & 31;
    const float* Vb = V + (size_t)bh * Lq * Dq;
    const float* Sb = g_scores + (size_t)bh * NT * Lq;
    float acc[5][2] = {};
    for (int sub = 0; sub < 2; sub++) {
        int k0 = ks * 256 + sub * 128;
        __syncthreads();
        for (int j = t; j < 128 * Dq; j += 256) Vs[j] = Vb[(size_t)k0 * Dq + j];
        __syncthreads();
        #pragma unroll 4
        for (int kk = 0; kk < 128; kk++) {
            float a[5];
            #pragma unroll
            for (int i = 0; i < 5; i++)
                a[i] = __ldg(&Sb[(size_t)(tu * 5 + i) * Lq + k0 + kk]);
            float2 v = *(const float2*)&Vs[kk * Dq + td * 2];
            #pragma unroll
            for (int i = 0; i < 5; i++) {
                acc[i][0] = fmaf(a[i], v.x, acc[i][0]);
                acc[i][1] = fmaf(a[i], v.y, acc[i][1]);
            }
        }
    }
    #pragma unroll
    for (int i = 0; i < 5; i++) {
        int u = tu * 5 + i;
        float2 r; r.x = acc[i][0]; r.y = acc[i][1];
        *(float2*)&g_part[(((size_t)ks * BH + bh) * NT + u) * Dq + td * 2] = r;
    }
}

// ---------------- kernel 8: sum partials * inv_sum, scatter --------------
__global__ void k_scatter(float* __restrict__ out) {
    int i = blockIdx.x * blockDim.x + threadIdx.x;   // BH*NT*D = 81920
    if (i >= BH * NT * Dq) return;
    int d = i & 63;
    int u = (i >> 6) % NT;
    int bh = (i >> 6) / NT;
    float s = 0.f;
    #pragma unroll
    for (int ks = 0; ks < 8; ks++)
        s += g_part[(((size_t)ks * BH + bh) * NT + u) * Dq + d];
    s *= g_inv[bh * NT + u];
    int qi = g_top[bh * NT + u];
    out[((size_t)bh * Lq + qi) * Dq + d] = s;
}

// ---------------- launch ---------------------------------------------------
extern "C" void kernel_launch(void* const* d_in, const int* in_sizes, int n_in,
                              void* d_out, int out_size) {
    const float* Q = (const float*)d_in[0];
    const float* K = (const float*)d_in[1];
    const float* V = (const float*)d_in[2];
    const int* idxs = (const int*)d_in[3];
    float* out = (float*)d_out;

    // order: k_topk (radix, never measured) is user launch #4 (profiled).
    k_vmean<<<BH, 256>>>(V);                             // 1
    k_M<<<(BH * Lq) / 8, 256>>>(Q, K, idxs);             // 2
    k_fill<<<(BH * Lq * Dq / 4) / 256, 256>>>((float4*)out); // 3
    k_topk<<<BH, 256>>>();                               // 4  <-- profiled
    k_scores<<<BH * 16, 512>>>(Q, K);                    // 5
    k_softmax<<<BH * NT, 256>>>();                       // 6
    k_ctx<<<BH * 8, 256>>>(V);                           // 7
    k_scatter<<<(BH * NT * Dq + 255) / 256, 256>>>(out); // 8
}

// round 9
// speedup vs baseline: 1.3939x; 1.2041x over previous
#include <cuda_runtime.h>
#include <cuda_bf16.h>
#include <math_constants.h>

// Problem constants (fixed by setup_inputs)
#define Bq 4
#define Hq 8
#define BH 32          // B*H
#define Lq 2048
#define Dq 64
#define SK 40          // sample_k
#define NT 40          // n_top
#define SCALE 0.125f   // 1/sqrt(64)

// ---------------- scratch (device globals; no allocation) ----------------
__device__ float g_M[BH * Lq];                 // 256 KB
__device__ int   g_top[BH * NT];               // 5 KB
__device__ float g_vmean[BH * Dq];             // 8 KB
__device__ float g_inv[BH * NT];               // per-row 1/softmax_sum
__device__ float g_scores[(size_t)BH * NT * Lq];   // 10.5 MB
__device__ float g_part[8 * BH * NT * Dq];     // 2.6 MB (k-split partials)

// ---------------- kernel 1: M[bh,l] = max_s q.k - sum_s/L ----------------
template<int O, int V>
__device__ __forceinline__ void fold(float* p, int lane) {
    bool hi = (lane & O) != 0;
    #pragma unroll
    for (int j = 0; j < V / 2; j++) {
        float send = hi ? p[j] : p[j + V / 2];
        float keep = hi ? p[j + V / 2] : p[j];
        p[j] = keep + __shfl_xor_sync(0xffffffffu, send, O);
    }
}

__device__ __forceinline__ float dot16(const float* __restrict__ Kb, float2 q,
                                       int e, int base, int lane) {
    float p[16];
    #pragma unroll
    for (int j = 0; j < 16; j++) {
        int idx = __shfl_sync(0xffffffffu, e, base + j);
        float2 k = ((const float2*)(Kb + (size_t)idx * Dq))[lane];
        p[j] = q.x * k.x + q.y * k.y;
    }
    fold<16, 16>(p, lane);
    fold<8, 8>(p, lane);
    fold<4, 4>(p, lane);
    fold<2, 2>(p, lane);
    p[0] += __shfl_xor_sync(0xffffffffu, p[0], 1);
    return p[0];
}

__device__ __forceinline__ float dot8(const float* __restrict__ Kb, float2 q,
                                      int e, int lane) {
    float p[8];
    #pragma unroll
    for (int j = 0; j < 8; j++) {
        int idx = __shfl_sync(0xffffffffu, e, j);
        float2 k = ((const float2*)(Kb + (size_t)idx * Dq))[lane];
        p[j] = q.x * k.x + q.y * k.y;
    }
    fold<16, 8>(p, lane);
    fold<8, 4>(p, lane);
    fold<4, 2>(p, lane);
    p[0] += __shfl_xor_sync(0xffffffffu, p[0], 2);
    p[0] += __shfl_xor_sync(0xffffffffu, p[0], 1);
    return p[0];
}

__global__ void k_M(const float* __restrict__ Q, const float* __restrict__ K,
                    const int* __restrict__ idxs) {
    int w = blockIdx.x * 8 + (threadIdx.x >> 5);   // query id (bh*2048 + l)
    int lane = threadIdx.x & 31;
    int bh = w >> 11;
    int l  = w & (Lq - 1);
    float2 q = ((const float2*)(Q + (size_t)w * Dq))[lane];
    const float* Kb = K + (size_t)bh * Lq * Dq;
    int e0 = idxs[l * SK + lane];
    int e1 = (lane < 8) ? idxs[l * SK + 32 + lane] : 0;

    float a = dot16(Kb, q, e0, 0, lane);
    float b = dot16(Kb, q, e0, 16, lane);
    float c = dot8(Kb, q, e1, lane);

    float mx = fmaxf(fmaxf(a, b), c);
    float sm = 0.5f * (a + b) + 0.25f * c;
    #pragma unroll
    for (int o = 16; o; o >>= 1) {
        mx = fmaxf(mx, __shfl_xor_sync(0xffffffffu, mx, o));
        sm += __shfl_xor_sync(0xffffffffu, sm, o);
    }
    if (lane == 0) g_M[w] = mx - sm * (1.0f / (float)Lq);
}

// ---------------- kernel 2: top-40 per (b,h), 4-level radix select -------
// Keys (order-flipped float bits) live in registers (8/thread). Each level
// refines one byte: per-warp histograms (no cross-warp atomic contention),
// shfl suffix-scan to locate boundary bin, emit bins above it. After 4
// levels the prefix is the exact rank-NT key; ties resolved by min index.
__global__ void k_topk() {
    __shared__ int hist[8][256];   // per-warp histograms
    __shared__ int suf[257];
    __shared__ int wred[8];
    __shared__ int s_T, s_cnt, s_min;
    int bh = blockIdx.x;
    int t = threadIdx.x, lane = t & 31, w = t >> 5;

    unsigned key[8];
    #pragma unroll
    for (int j = 0; j < 8; j++) {
        unsigned u = __float_as_uint(g_M[bh * Lq + t * 8 + j]);
        key[j] = (u & 0x80000000u) ? ~u : (u | 0x80000000u);
    }
    unsigned prefix = 0;
    int need = NT;
    if (t == 0) s_cnt = 0;

    #pragma unroll
    for (int level = 0; level < 4; level++) {
        int shift = 24 - 8 * level;
        for (int b = t; b < 8 * 256; b += 256) (&hist[0][0])[b] = 0;
        __syncthreads();
        #pragma unroll
        for (int j = 0; j < 8; j++) {
            bool match = (level == 0) || ((key[j] >> (shift + 8)) == prefix);
            if (match) atomicAdd(&hist[w][(key[j] >> shift) & 255u], 1);
        }
        __syncthreads();
        int h = 0;
        #pragma unroll
        for (int ww = 0; ww < 8; ww++) h += hist[ww][t];
        // intra-warp inclusive suffix over this warp's 32 bins
        int sv = h;
        #pragma unroll
        for (int off = 1; off < 32; off <<= 1) {
            int v = __shfl_down_sync(0xffffffffu, sv, off);
            if (lane + off < 32) sv += v;
        }
        int wtot = __shfl_sync(0xffffffffu, sv, 0);
        if (lane == 0) wred[w] = wtot;
        __syncthreads();
        int higher = 0;
        #pragma unroll
        for (int ww = 0; ww < 8; ww++) if (ww > w) higher += wred[ww];
        suf[t] = sv + higher;              // count of matching keys with bin >= t
        if (t == 0) suf[256] = 0;
        __syncthreads();
        if (suf[t] >= need && suf[t + 1] < need) s_T = t;   // unique t
        __syncthreads();
        int T = s_T;
        #pragma unroll
        for (int j = 0; j < 8; j++) {
            bool match = (level == 0) || ((key[j] >> (shift + 8)) == prefix);
            if (match && (int)((key[j] >> shift) & 255u) > T) {
                int p = atomicAdd(&s_cnt, 1);
                g_top[bh * NT + p] = t * 8 + j;
            }
        }
        need -= suf[T + 1];                // accepted this level
        prefix = (prefix << 8) | (unsigned)T;
        __syncthreads();
    }

    // tie-break: keys exactly equal to threshold; take ascending indices.
    for (int it = 0; it < need; it++) {
        int mi = Lq;
        #pragma unroll
        for (int j = 0; j < 8; j++)
            if (key[j] == prefix) mi = min(mi, t * 8 + j);
        #pragma unroll
        for (int off = 16; off; off >>= 1)
            mi = min(mi, __shfl_xor_sync(0xffffffffu, mi, off));
        if (lane == 0) wred[w] = mi;
        __syncthreads();
        if (t == 0) {
            int m = wred[0];
            #pragma unroll
            for (int ww = 1; ww < 8; ww++) m = min(m, wred[ww]);
            s_min = m;
            g_top[bh * NT + (NT - need) + it] = m;
        }
        __syncthreads();
        int m = s_min;
        if (m >= t * 8 && m < t * 8 + 8) key[m - t * 8] = 0u;  // 0 unreachable for finite M
        __syncthreads();
    }
}

// ---------------- kernel 3: V mean over L per (b,h), float4 --------------
__global__ void k_vmean(const float* __restrict__ V) {
    __shared__ float4 ps[256];
    int bh = blockIdx.x;
    int t = threadIdx.x;               // 256
    int d4 = t & 15, part = t >> 4;    // 16 parts x 128 rows
    const float4* Vb = (const float4*)(V + (size_t)bh * Lq * Dq);
    float4 s = make_float4(0.f, 0.f, 0.f, 0.f);
    int k0 = part * 128;
    for (int k = k0; k < k0 + 128; k++) {
        float4 v = Vb[(size_t)k * 16 + d4];
        s.x += v.x; s.y += v.y; s.z += v.z; s.w += v.w;
    }
    ps[t] = s;
    __syncthreads();
    if (t < 16) {
        float4 a = ps[t];
        #pragma unroll
        for (int pI = 1; pI < 16; pI++) {
            float4 v = ps[pI * 16 + t];
            a.x += v.x; a.y += v.y; a.z += v.z; a.w += v.w;
        }
        const float inv = 1.0f / (float)Lq;
        a.x *= inv; a.y *= inv; a.z *= inv; a.w *= inv;
        ((float4*)g_vmean)[bh * 16 + t] = a;
    }
}

// ---------------- kernel 4: broadcast V_mean (wide grid) -----------------
__global__ void k_fill(float4* __restrict__ out4) {
    int i = blockIdx.x * 256 + threadIdx.x;  // BH*L*16 float4s
    int bh = i >> 15;
    int d4 = i & 15;
    out4[i] = ((const float4*)g_vmean)[bh * 16 + d4];
}

// ---------------- kernel 5: scores = (Q_top @ K^T) * scale ---------------
// 128-key tile, 512 threads (16 warps); grid BH*16 = 512 blocks.
__global__ void k_scores(const float* __restrict__ Q, const float* __restrict__ K) {
    __shared__ float qs[NT * Dq];           // 10 KB
    __shared__ float Kt[Dq * 132];          // transposed [d][k], pad 132
    int bh = blockIdx.x >> 4;
    int kt = blockIdx.x & 15;
    int t = threadIdx.x;                    // 512
    const float* Qb = Q + (size_t)bh * Lq * Dq;
    const float* Kb = K + (size_t)bh * Lq * Dq;
    for (int j = t; j < NT * Dq; j += 512) {
        int u = j >> 6, d = j & 63;
        int qi = __ldg(&g_top[bh * NT + u]);
        qs[j] = Qb[(size_t)qi * Dq + d];
    }
    for (int j = t; j < 128 * Dq; j += 512) {
        int r = j >> 6, d = j & 63;
        Kt[d * 132 + r] = Kb[(size_t)(kt * 128 + r) * Dq + d];
    }
    __syncthreads();
    int w = t >> 5, lane = t & 31;
    int wq = w >> 1;                        // 8 query groups of 5
    int kh = (w & 1) * 64;                  // key half
    float acc[5][2] = {};
    #pragma unroll 8
    for (int d = 0; d < Dq; d++) {
        float a[5];
        #pragma unroll
        for (int i = 0; i < 5; i++) a[i] = qs[(wq * 5 + i) * Dq + d];
        float2 b = *(const float2*)&Kt[d * 132 + kh + lane * 2];
        #pragma unroll
        for (int i = 0; i < 5; i++) {
            acc[i][0] = fmaf(a[i], b.x, acc[i][0]);
            acc[i][1] = fmaf(a[i], b.y, acc[i][1]);
        }
    }
    #pragma unroll
    for (int i = 0; i < 5; i++) {
        int u = wq * 5 + i;
        float2 r;
        r.x = acc[i][0] * SCALE; r.y = acc[i][1] * SCALE;
        *(float2*)&g_scores[((size_t)(bh * NT + u)) * Lq + kt * 128 + kh + lane * 2] = r;
    }
}

// ---------------- kernel 6: softmax 2-pass (exp write + 1/sum) -----------
__global__ void k_softmax() {
    __shared__ float red[8];
    int row = blockIdx.x;                  // BH*NT = 1280 rows
    float* s = g_scores + (size_t)row * Lq;
    int t = threadIdx.x, lane = t & 31, wid = t >> 5;
    float mx = -CUDART_INF_F;
    for (int i = t; i < Lq; i += 256) mx = fmaxf(mx, s[i]);
    #pragma unroll
    for (int o = 16; o; o >>= 1) mx = fmaxf(mx, __shfl_xor_sync(0xffffffffu, mx, o));
    if (lane == 0) red[wid] = mx;
    __syncthreads();
    mx = red[0];
    #pragma unroll
    for (int i = 1; i < 8; i++) mx = fmaxf(mx, red[i]);
    __syncthreads();
    float sum = 0.f;
    for (int i = t; i < Lq; i += 256) {
        float e = __expf(s[i] - mx);
        s[i] = e;
        sum += e;
    }
    #pragma unroll
    for (int o = 16; o; o >>= 1) sum += __shfl_xor_sync(0xffffffffu, sum, o);
    if (lane == 0) red[wid] = sum;
    __syncthreads();
    if (t == 0) {
        sum = 0.f;
        #pragma unroll
        for (int i = 0; i < 8; i++) sum += red[i];
        g_inv[row] = 1.0f / sum;
    }
}

// ---------------- kernel 7: ctx partial = exp_scores @ V (k-split) -------
__global__ void k_ctx(const float* __restrict__ V) {
    __shared__ float Vs[128 * Dq];          // 32 KB
    int bh = blockIdx.x >> 3;
    int ks = blockIdx.x & 7;
    int t = threadIdx.x;
    int tu = t >> 5;
    int td = t & 31;
    const float* Vb = V + (size_t)bh * Lq * Dq;
    const float* Sb = g_scores + (size_t)bh * NT * Lq;
    float acc[5][2] = {};
    for (int sub = 0; sub < 2; sub++) {
        int k0 = ks * 256 + sub * 128;
        __syncthreads();
        for (int j = t; j < 128 * Dq; j += 256) Vs[j] = Vb[(size_t)k0 * Dq + j];
        __syncthreads();
        #pragma unroll 4
        for (int kk = 0; kk < 128; kk++) {
            float a[5];
            #pragma unroll
            for (int i = 0; i < 5; i++)
                a[i] = __ldg(&Sb[(size_t)(tu * 5 + i) * Lq + k0 + kk]);
            float2 v = *(const float2*)&Vs[kk * Dq + td * 2];
            #pragma unroll
            for (int i = 0; i < 5; i++) {
                acc[i][0] = fmaf(a[i], v.x, acc[i][0]);
                acc[i][1] = fmaf(a[i], v.y, acc[i][1]);
            }
        }
    }
    #pragma unroll
    for (int i = 0; i < 5; i++) {
        int u = tu * 5 + i;
        float2 r; r.x = acc[i][0]; r.y = acc[i][1];
        *(float2*)&g_part[(((size_t)ks * BH + bh) * NT + u) * Dq + td * 2] = r;
    }
}

// ---------------- kernel 8: sum partials * inv_sum, scatter --------------
__global__ void k_scatter(float* __restrict__ out) {
    int i = blockIdx.x * blockDim.x + threadIdx.x;   // BH*NT*D = 81920
    if (i >= BH * NT * Dq) return;
    int d = i & 63;
    int u = (i >> 6) % NT;
    int bh = (i >> 6) / NT;
    float s = 0.f;
    #pragma unroll
    for (int ks = 0; ks < 8; ks++)
        s += g_part[(((size_t)ks * BH + bh) * NT + u) * Dq + d];
    s *= g_inv[bh * NT + u];
    int qi = g_top[bh * NT + u];
    out[((size_t)bh * Lq + qi) * Dq + d] = s;
}

// ---------------- launch ---------------------------------------------------
extern "C" void kernel_launch(void* const* d_in, const int* in_sizes, int n_in,
                              void* d_out, int out_size) {
    const float* Q = (const float*)d_in[0];
    const float* K = (const float*)d_in[1];
    const float* V = (const float*)d_in[2];
    const int* idxs = (const int*)d_in[3];
    float* out = (float*)d_out;

    // order: k_scores (512t version, unprofiled) is user launch #4.
    k_vmean<<<BH, 256>>>(V);                             // 1
    k_M<<<(BH * Lq) / 8, 256>>>(Q, K, idxs);             // 2
    k_topk<<<BH, 256>>>();                               // 3
    k_scores<<<BH * 16, 512>>>(Q, K);                    // 4  <-- profiled
    k_fill<<<(BH * Lq * Dq / 4) / 256, 256>>>((float4*)out); // 5
    k_softmax<<<BH * NT, 256>>>();                       // 6
    k_ctx<<<BH * 8, 256>>>(V);                           // 7
    k_scatter<<<(BH * NT * Dq + 255) / 256, 256>>>(out); // 8
}

// round 10
// speedup vs baseline: 1.4174x; 1.0169x over previous
#include <cuda_runtime.h>
#include <cuda_bf16.h>
#include <math_constants.h>

// Problem constants (fixed by setup_inputs)
#define Bq 4
#define Hq 8
#define BH 32          // B*H
#define Lq 2048
#define Dq 64
#define SK 40          // sample_k
#define NT 40          // n_top
#define SCALE 0.125f   // 1/sqrt(64)

// ---------------- scratch (device globals; no allocation) ----------------
__device__ float g_M[BH * Lq];                 // 256 KB
__device__ int   g_top[BH * NT];               // 5 KB
__device__ float g_vmean[BH * Dq];             // 8 KB
__device__ float g_inv[BH * NT];               // per-row 1/softmax_sum
__device__ float g_scores[(size_t)BH * NT * Lq];   // 10.5 MB
__device__ float g_part[8 * BH * NT * Dq];     // 2.6 MB (k-split partials)

// ---------------- kernel 1: M[bh,l] = max_s q.k - sum_s/L ----------------
template<int O, int V>
__device__ __forceinline__ void fold(float* p, int lane) {
    bool hi = (lane & O) != 0;
    #pragma unroll
    for (int j = 0; j < V / 2; j++) {
        float send = hi ? p[j] : p[j + V / 2];
        float keep = hi ? p[j + V / 2] : p[j];
        p[j] = keep + __shfl_xor_sync(0xffffffffu, send, O);
    }
}

__device__ __forceinline__ float dot16(const float* __restrict__ Kb, float2 q,
                                       int e, int base, int lane) {
    float p[16];
    #pragma unroll
    for (int j = 0; j < 16; j++) {
        int idx = __shfl_sync(0xffffffffu, e, base + j);
        float2 k = ((const float2*)(Kb + (size_t)idx * Dq))[lane];
        p[j] = q.x * k.x + q.y * k.y;
    }
    fold<16, 16>(p, lane);
    fold<8, 8>(p, lane);
    fold<4, 4>(p, lane);
    fold<2, 2>(p, lane);
    p[0] += __shfl_xor_sync(0xffffffffu, p[0], 1);
    return p[0];
}

__device__ __forceinline__ float dot8(const float* __restrict__ Kb, float2 q,
                                      int e, int lane) {
    float p[8];
    #pragma unroll
    for (int j = 0; j < 8; j++) {
        int idx = __shfl_sync(0xffffffffu, e, j);
        float2 k = ((const float2*)(Kb + (size_t)idx * Dq))[lane];
        p[j] = q.x * k.x + q.y * k.y;
    }
    fold<16, 8>(p, lane);
    fold<8, 4>(p, lane);
    fold<4, 2>(p, lane);
    p[0] += __shfl_xor_sync(0xffffffffu, p[0], 2);
    p[0] += __shfl_xor_sync(0xffffffffu, p[0], 1);
    return p[0];
}

__global__ void k_M(const float* __restrict__ Q, const float* __restrict__ K,
                    const int* __restrict__ idxs) {
    int w = blockIdx.x * 8 + (threadIdx.x >> 5);   // query id (bh*2048 + l)
    int lane = threadIdx.x & 31;
    int bh = w >> 11;
    int l  = w & (Lq - 1);
    float2 q = ((const float2*)(Q + (size_t)w * Dq))[lane];
    const float* Kb = K + (size_t)bh * Lq * Dq;
    int e0 = idxs[l * SK + lane];
    int e1 = (lane < 8) ? idxs[l * SK + 32 + lane] : 0;

    float a = dot16(Kb, q, e0, 0, lane);
    float b = dot16(Kb, q, e0, 16, lane);
    float c = dot8(Kb, q, e1, lane);

    float mx = fmaxf(fmaxf(a, b), c);
    float sm = 0.5f * (a + b) + 0.25f * c;
    #pragma unroll
    for (int o = 16; o; o >>= 1) {
        mx = fmaxf(mx, __shfl_xor_sync(0xffffffffu, mx, o));
        sm += __shfl_xor_sync(0xffffffffu, sm, o);
    }
    if (lane == 0) g_M[w] = mx - sm * (1.0f / (float)Lq);
}

// ---------------- kernel 2: top-40 per (b,h), 4-level radix select -------
__global__ void k_topk() {
    __shared__ int hist[8][256];   // per-warp histograms
    __shared__ int suf[257];
    __shared__ int wred[8];
    __shared__ int s_T, s_cnt, s_min;
    int bh = blockIdx.x;
    int t = threadIdx.x, lane = t & 31, w = t >> 5;

    unsigned key[8];
    #pragma unroll
    for (int j = 0; j < 8; j++) {
        unsigned u = __float_as_uint(g_M[bh * Lq + t * 8 + j]);
        key[j] = (u & 0x80000000u) ? ~u : (u | 0x80000000u);
    }
    unsigned prefix = 0;
    int need = NT;
    if (t == 0) s_cnt = 0;

    #pragma unroll
    for (int level = 0; level < 4; level++) {
        int shift = 24 - 8 * level;
        for (int b = t; b < 8 * 256; b += 256) (&hist[0][0])[b] = 0;
        __syncthreads();
        #pragma unroll
        for (int j = 0; j < 8; j++) {
            bool match = (level == 0) || ((key[j] >> (shift + 8)) == prefix);
            if (match) atomicAdd(&hist[w][(key[j] >> shift) & 255u], 1);
        }
        __syncthreads();
        int h = 0;
        #pragma unroll
        for (int ww = 0; ww < 8; ww++) h += hist[ww][t];
        int sv = h;
        #pragma unroll
        for (int off = 1; off < 32; off <<= 1) {
            int v = __shfl_down_sync(0xffffffffu, sv, off);
            if (lane + off < 32) sv += v;
        }
        int wtot = __shfl_sync(0xffffffffu, sv, 0);
        if (lane == 0) wred[w] = wtot;
        __syncthreads();
        int higher = 0;
        #pragma unroll
        for (int ww = 0; ww < 8; ww++) if (ww > w) higher += wred[ww];
        suf[t] = sv + higher;
        if (t == 0) suf[256] = 0;
        __syncthreads();
        if (suf[t] >= need && suf[t + 1] < need) s_T = t;
        __syncthreads();
        int T = s_T;
        #pragma unroll
        for (int j = 0; j < 8; j++) {
            bool match = (level == 0) || ((key[j] >> (shift + 8)) == prefix);
            if (match && (int)((key[j] >> shift) & 255u) > T) {
                int p = atomicAdd(&s_cnt, 1);
                g_top[bh * NT + p] = t * 8 + j;
            }
        }
        need -= suf[T + 1];
        prefix = (prefix << 8) | (unsigned)T;
        __syncthreads();
    }

    for (int it = 0; it < need; it++) {
        int mi = Lq;
        #pragma unroll
        for (int j = 0; j < 8; j++)
            if (key[j] == prefix) mi = min(mi, t * 8 + j);
        #pragma unroll
        for (int off = 16; off; off >>= 1)
            mi = min(mi, __shfl_xor_sync(0xffffffffu, mi, off));
        if (lane == 0) wred[w] = mi;
        __syncthreads();
        if (t == 0) {
            int m = wred[0];
            #pragma unroll
            for (int ww = 1; ww < 8; ww++) m = min(m, wred[ww]);
            s_min = m;
            g_top[bh * NT + (NT - need) + it] = m;
        }
        __syncthreads();
        int m = s_min;
        if (m >= t * 8 && m < t * 8 + 8) key[m - t * 8] = 0u;
        __syncthreads();
    }
}

// ---------------- kernel 3: V mean over L per (b,h), float4 --------------
__global__ void k_vmean(const float* __restrict__ V) {
    __shared__ float4 ps[256];
    int bh = blockIdx.x;
    int t = threadIdx.x;               // 256
    int d4 = t & 15, part = t >> 4;    // 16 parts x 128 rows
    const float4* Vb = (const float4*)(V + (size_t)bh * Lq * Dq);
    float4 s = make_float4(0.f, 0.f, 0.f, 0.f);
    int k0 = part * 128;
    for (int k = k0; k < k0 + 128; k++) {
        float4 v = Vb[(size_t)k * 16 + d4];
        s.x += v.x; s.y += v.y; s.z += v.z; s.w += v.w;
    }
    ps[t] = s;
    __syncthreads();
    if (t < 16) {
        float4 a = ps[t];
        #pragma unroll
        for (int pI = 1; pI < 16; pI++) {
            float4 v = ps[pI * 16 + t];
            a.x += v.x; a.y += v.y; a.z += v.z; a.w += v.w;
        }
        const float inv = 1.0f / (float)Lq;
        a.x *= inv; a.y *= inv; a.z *= inv; a.w *= inv;
        ((float4*)g_vmean)[bh * 16 + t] = a;
    }
}

// ---------------- kernel 4: broadcast V_mean (wide grid, 2 halves) -------
__global__ void k_fill(float4* __restrict__ out4, int base) {
    int i = base + blockIdx.x * 256 + threadIdx.x;
    int bh = i >> 15;
    int d4 = i & 15;
    out4[i] = ((const float4*)g_vmean)[bh * 16 + d4];
}

// ---------------- kernel 5: scores = (Q_top @ K^T) * scale ---------------
// 128-key tile, 512 threads. d processed in float4 chunks: q loaded via
// LDS.128 broadcast (4x fewer q loads), 40 independent FMAs per chunk.
__global__ void k_scores(const float* __restrict__ Q, const float* __restrict__ K) {
    __shared__ float qs[NT * Dq];           // 10 KB
    __shared__ float Kt[Dq * 132];          // transposed [d][k], pad 132
    int bh = blockIdx.x >> 4;
    int kt = blockIdx.x & 15;
    int t = threadIdx.x;                    // 512
    const float* Qb = Q + (size_t)bh * Lq * Dq;
    const float* Kb = K + (size_t)bh * Lq * Dq;
    for (int j = t; j < NT * Dq; j += 512) {
        int u = j >> 6, d = j & 63;
        int qi = __ldg(&g_top[bh * NT + u]);
        qs[j] = Qb[(size_t)qi * Dq + d];
    }
    for (int j = t; j < 128 * Dq; j += 512) {
        int r = j >> 6, d = j & 63;
        Kt[d * 132 + r] = Kb[(size_t)(kt * 128 + r) * Dq + d];
    }
    __syncthreads();
    int w = t >> 5, lane = t & 31;
    int wq = w >> 1;                        // 8 query groups of 5
    int kh = (w & 1) * 64;                  // key half
    float acc[5][2] = {};
    #pragma unroll
    for (int dc = 0; dc < Dq; dc += 4) {
        float4 a[5];
        #pragma unroll
        for (int i = 0; i < 5; i++)
            a[i] = *(const float4*)&qs[(wq * 5 + i) * Dq + dc];
        #pragma unroll
        for (int j = 0; j < 4; j++) {
            float2 b = *(const float2*)&Kt[(dc + j) * 132 + kh + lane * 2];
            float aj;
            #pragma unroll
            for (int i = 0; i < 5; i++) {
                aj = (j == 0) ? a[i].x : (j == 1) ? a[i].y : (j == 2) ? a[i].z : a[i].w;
                acc[i][0] = fmaf(aj, b.x, acc[i][0]);
                acc[i][1] = fmaf(aj, b.y, acc[i][1]);
            }
        }
    }
    #pragma unroll
    for (int i = 0; i < 5; i++) {
        int u = wq * 5 + i;
        float2 r;
        r.x = acc[i][0] * SCALE; r.y = acc[i][1] * SCALE;
        *(float2*)&g_scores[((size_t)(bh * NT + u)) * Lq + kt * 128 + kh + lane * 2] = r;
    }
}

// ---------------- kernel 6: softmax 2-pass, float4 (exp write + 1/sum) ---
__global__ void k_softmax() {
    __shared__ float red[8];
    int row = blockIdx.x;                  // BH*NT = 1280 rows
    float4* s4 = (float4*)(g_scores + (size_t)row * Lq);
    int t = threadIdx.x, lane = t & 31, wid = t >> 5;
    // each thread owns 2 float4s (8 floats)
    float4 v0 = s4[t * 2], v1 = s4[t * 2 + 1];
    float mx = fmaxf(fmaxf(fmaxf(v0.x, v0.y), fmaxf(v0.z, v0.w)),
                     fmaxf(fmaxf(v1.x, v1.y), fmaxf(v1.z, v1.w)));
    #pragma unroll
    for (int o = 16; o; o >>= 1) mx = fmaxf(mx, __shfl_xor_sync(0xffffffffu, mx, o));
    if (lane == 0) red[wid] = mx;
    __syncthreads();
    mx = red[0];
    #pragma unroll
    for (int i = 1; i < 8; i++) mx = fmaxf(mx, red[i]);
    v0.x = __expf(v0.x - mx); v0.y = __expf(v0.y - mx);
    v0.z = __expf(v0.z - mx); v0.w = __expf(v0.w - mx);
    v1.x = __expf(v1.x - mx); v1.y = __expf(v1.y - mx);
    v1.z = __expf(v1.z - mx); v1.w = __expf(v1.w - mx);
    s4[t * 2] = v0; s4[t * 2 + 1] = v1;
    float sum = (v0.x + v0.y + v0.z + v0.w) + (v1.x + v1.y + v1.z + v1.w);
    #pragma unroll
    for (int o = 16; o; o >>= 1) sum += __shfl_xor_sync(0xffffffffu, sum, o);
    __syncthreads();
    if (lane == 0) red[wid] = sum;
    __syncthreads();
    if (t == 0) {
        sum = 0.f;
        #pragma unroll
        for (int i = 0; i < 8; i++) sum += red[i];
        g_inv[row] = 1.0f / sum;
    }
}

// ---------------- kernel 7: ctx partial = exp_scores @ V (k-split) -------
// float4 score loads: 4 kk-steps per LDG.128.
__global__ void k_ctx(const float* __restrict__ V) {
    __shared__ float Vs[128 * Dq];          // 32 KB
    int bh = blockIdx.x >> 3;
    int ks = blockIdx.x & 7;
    int t = threadIdx.x;
    int tu = t >> 5;
    int td = t & 31;
    const float* Vb = V + (size_t)bh * Lq * Dq;
    const float* Sb = g_scores + (size_t)bh * NT * Lq;
    float acc[5][2] = {};
    for (int sub = 0; sub < 2; sub++) {
        int k0 = ks * 256 + sub * 128;
        __syncthreads();
        for (int j = t; j < 128 * Dq; j += 256) Vs[j] = Vb[(size_t)k0 * Dq + j];
        __syncthreads();
        #pragma unroll 2
        for (int kk = 0; kk < 128; kk += 4) {
            float4 a[5];
            #pragma unroll
            for (int i = 0; i < 5; i++)
                a[i] = *(const float4*)&Sb[(size_t)(tu * 5 + i) * Lq + k0 + kk];
            #pragma unroll
            for (int j = 0; j < 4; j++) {
                float2 v = *(const float2*)&Vs[(kk + j) * Dq + td * 2];
                #pragma unroll
                for (int i = 0; i < 5; i++) {
                    float aj = (j == 0) ? a[i].x : (j == 1) ? a[i].y : (j == 2) ? a[i].z : a[i].w;
                    acc[i][0] = fmaf(aj, v.x, acc[i][0]);
                    acc[i][1] = fmaf(aj, v.y, acc[i][1]);
                }
            }
        }
    }
    #pragma unroll
    for (int i = 0; i < 5; i++) {
        int u = tu * 5 + i;
        float2 r; r.x = acc[i][0]; r.y = acc[i][1];
        *(float2*)&g_part[(((size_t)ks * BH + bh) * NT + u) * Dq + td * 2] = r;
    }
}

// ---------------- kernel 8: sum partials * inv_sum, scatter --------------
__global__ void k_scatter(float* __restrict__ out) {
    int i = blockIdx.x * blockDim.x + threadIdx.x;   // BH*NT*D = 81920
    if (i >= BH * NT * Dq) return;
    int d = i & 63;
    int u = (i >> 6) % NT;
    int bh = (i >> 6) / NT;
    float s = 0.f;
    #pragma unroll
    for (int ks = 0; ks < 8; ks++)
        s += g_part[(((size_t)ks * BH + bh) * NT + u) * Dq + d];
    s *= g_inv[bh * NT + u];
    int qi = g_top[bh * NT + u];
    out[((size_t)bh * Lq + qi) * Dq + d] = s;
}

// ---------------- launch ---------------------------------------------------
extern "C" void kernel_launch(void* const* d_in, const int* in_sizes, int n_in,
                              void* d_out, int out_size) {
    const float* Q = (const float*)d_in[0];
    const float* K = (const float*)d_in[1];
    const float* V = (const float*)d_in[2];
    const int* idxs = (const int*)d_in[3];
    float* out = (float*)d_out;

    // order: k_M (post-fold version) is user launch #4 (profiled).
    const int NF4 = BH * Lq * Dq / 4;
    k_vmean<<<BH, 256>>>(V);                                  // 1
    k_fill<<<NF4 / 2 / 256, 256>>>((float4*)out, 0);          // 2
    k_fill<<<NF4 / 2 / 256, 256>>>((float4*)out, NF4 / 2);    // 3
    k_M<<<(BH * Lq) / 8, 256>>>(Q, K, idxs);                  // 4  <-- profiled
    k_topk<<<BH, 256>>>();                                    // 5
    k_scores<<<BH * 16, 512>>>(Q, K);                         // 6
    k_softmax<<<BH * NT, 256>>>();                            // 7
    k_ctx<<<BH * 8, 256>>>(V);                                // 8
    k_scatter<<<(BH * NT * Dq + 255) / 256, 256>>>(out);      // 9
}

// round 11
// speedup vs baseline: 1.5186x; 1.0714x over previous
#include <cuda_runtime.h>
#include <cuda_bf16.h>
#include <math_constants.h>

// Problem constants (fixed by setup_inputs)
#define Bq 4
#define Hq 8
#define BH 32          // B*H
#define Lq 2048
#define Dq 64
#define SK 40          // sample_k
#define NT 40          // n_top
#define SCALE 0.125f   // 1/sqrt(64)

// ---------------- scratch (device globals; no allocation) ----------------
__device__ float g_M[BH * Lq];                 // 256 KB
__device__ int   g_top[BH * NT];               // 5 KB
__device__ float g_vmean[BH * Dq];             // 8 KB
__device__ float g_inv[BH * NT];               // per-row 1/softmax_sum
__device__ float g_scores[(size_t)BH * NT * Lq];   // 10.5 MB
__device__ float g_part[8 * BH * NT * Dq];     // 2.6 MB (k-split partials)

// Fast exp on the FMA pipe: exp(x) = 2^(x*log2e), 2^f by deg-6 Taylor +
// exponent-bit scale. |rel err| ~1e-7 for the x<=0 softmax range.
__device__ __forceinline__ float fexpf(float x) {
    float y = x * 1.4426950408889634f;
    y = fmaxf(y, -125.0f);
    float r = rintf(y);
    float f = y - r;
    float p = 1.5403530e-4f;
    p = fmaf(p, f, 1.3333558e-3f);
    p = fmaf(p, f, 9.6181291e-3f);
    p = fmaf(p, f, 5.5504109e-2f);
    p = fmaf(p, f, 2.4022651e-1f);
    p = fmaf(p, f, 6.9314718e-1f);
    p = fmaf(p, f, 1.0f);
    return p * __int_as_float(((int)r + 127) << 23);
}

// ---------------- kernel 1: M[bh,l] = max_s q.k - sum_s/L ----------------
template<int O, int V>
__device__ __forceinline__ void fold(float* p, int lane) {
    bool hi = (lane & O) != 0;
    #pragma unroll
    for (int j = 0; j < V / 2; j++) {
        float send = hi ? p[j] : p[j + V / 2];
        float keep = hi ? p[j + V / 2] : p[j];
        p[j] = keep + __shfl_xor_sync(0xffffffffu, send, O);
    }
}

__device__ __forceinline__ float dot16(const float* __restrict__ Kb, float2 q,
                                       int e, int base, int lane) {
    float p[16];
    #pragma unroll
    for (int j = 0; j < 16; j++) {
        int idx = __shfl_sync(0xffffffffu, e, base + j);
        float2 k = ((const float2*)(Kb + (size_t)idx * Dq))[lane];
        p[j] = q.x * k.x + q.y * k.y;
    }
    fold<16, 16>(p, lane);
    fold<8, 8>(p, lane);
    fold<4, 4>(p, lane);
    fold<2, 2>(p, lane);
    p[0] += __shfl_xor_sync(0xffffffffu, p[0], 1);
    return p[0];
}

__device__ __forceinline__ float dot8(const float* __restrict__ Kb, float2 q,
                                      int e, int lane) {
    float p[8];
    #pragma unroll
    for (int j = 0; j < 8; j++) {
        int idx = __shfl_sync(0xffffffffu, e, j);
        float2 k = ((const float2*)(Kb + (size_t)idx * Dq))[lane];
        p[j] = q.x * k.x + q.y * k.y;
    }
    fold<16, 8>(p, lane);
    fold<8, 4>(p, lane);
    fold<4, 2>(p, lane);
    p[0] += __shfl_xor_sync(0xffffffffu, p[0], 2);
    p[0] += __shfl_xor_sync(0xffffffffu, p[0], 1);
    return p[0];
}

__global__ void k_M(const float* __restrict__ Q, const float* __restrict__ K,
                    const int* __restrict__ idxs) {
    int w = blockIdx.x * 8 + (threadIdx.x >> 5);   // query id (bh*2048 + l)
    int lane = threadIdx.x & 31;
    int bh = w >> 11;
    int l  = w & (Lq - 1);
    float2 q = ((const float2*)(Q + (size_t)w * Dq))[lane];
    const float* Kb = K + (size_t)bh * Lq * Dq;
    int e0 = idxs[l * SK + lane];
    int e1 = (lane < 8) ? idxs[l * SK + 32 + lane] : 0;

    float a = dot16(Kb, q, e0, 0, lane);
    float b = dot16(Kb, q, e0, 16, lane);
    float c = dot8(Kb, q, e1, lane);

    float mx = fmaxf(fmaxf(a, b), c);
    float sm = 0.5f * (a + b) + 0.25f * c;
    #pragma unroll
    for (int o = 16; o; o >>= 1) {
        mx = fmaxf(mx, __shfl_xor_sync(0xffffffffu, mx, o));
        sm += __shfl_xor_sync(0xffffffffu, sm, o);
    }
    if (lane == 0) g_M[w] = mx - sm * (1.0f / (float)Lq);
}

// ---------------- kernel 2: top-40 per (b,h), 4-level radix select -------
__global__ void k_topk() {
    __shared__ int hist[8][256];   // per-warp histograms
    __shared__ int suf[257];
    __shared__ int wred[8];
    __shared__ int s_T, s_cnt, s_min;
    int bh = blockIdx.x;
    int t = threadIdx.x, lane = t & 31, w = t >> 5;

    unsigned key[8];
    #pragma unroll
    for (int j = 0; j < 8; j++) {
        unsigned u = __float_as_uint(g_M[bh * Lq + t * 8 + j]);
        key[j] = (u & 0x80000000u) ? ~u : (u | 0x80000000u);
    }
    unsigned prefix = 0;
    int need = NT;
    if (t == 0) s_cnt = 0;

    #pragma unroll
    for (int level = 0; level < 4; level++) {
        int shift = 24 - 8 * level;
        for (int b = t; b < 8 * 256; b += 256) (&hist[0][0])[b] = 0;
        __syncthreads();
        #pragma unroll
        for (int j = 0; j < 8; j++) {
            bool match = (level == 0) || ((key[j] >> (shift + 8)) == prefix);
            if (match) atomicAdd(&hist[w][(key[j] >> shift) & 255u], 1);
        }
        __syncthreads();
        int h = 0;
        #pragma unroll
        for (int ww = 0; ww < 8; ww++) h += hist[ww][t];
        int sv = h;
        #pragma unroll
        for (int off = 1; off < 32; off <<= 1) {
            int v = __shfl_down_sync(0xffffffffu, sv, off);
            if (lane + off < 32) sv += v;
        }
        int wtot = __shfl_sync(0xffffffffu, sv, 0);
        if (lane == 0) wred[w] = wtot;
        __syncthreads();
        int higher = 0;
        #pragma unroll
        for (int ww = 0; ww < 8; ww++) if (ww > w) higher += wred[ww];
        suf[t] = sv + higher;
        if (t == 0) suf[256] = 0;
        __syncthreads();
        if (suf[t] >= need && suf[t + 1] < need) s_T = t;
        __syncthreads();
        int T = s_T;
        #pragma unroll
        for (int j = 0; j < 8; j++) {
            bool match = (level == 0) || ((key[j] >> (shift + 8)) == prefix);
            if (match && (int)((key[j] >> shift) & 255u) > T) {
                int p = atomicAdd(&s_cnt, 1);
                g_top[bh * NT + p] = t * 8 + j;
            }
        }
        need -= suf[T + 1];
        prefix = (prefix << 8) | (unsigned)T;
        __syncthreads();
    }

    for (int it = 0; it < need; it++) {
        int mi = Lq;
        #pragma unroll
        for (int j = 0; j < 8; j++)
            if (key[j] == prefix) mi = min(mi, t * 8 + j);
        #pragma unroll
        for (int off = 16; off; off >>= 1)
            mi = min(mi, __shfl_xor_sync(0xffffffffu, mi, off));
        if (lane == 0) wred[w] = mi;
        __syncthreads();
        if (t == 0) {
            int m = wred[0];
            #pragma unroll
            for (int ww = 1; ww < 8; ww++) m = min(m, wred[ww]);
            s_min = m;
            g_top[bh * NT + (NT - need) + it] = m;
        }
        __syncthreads();
        int m = s_min;
        if (m >= t * 8 && m < t * 8 + 8) key[m - t * 8] = 0u;
        __syncthreads();
    }
}

// ---------------- kernel 3: V mean over L per (b,h), float4 --------------
__global__ void k_vmean(const float* __restrict__ V) {
    __shared__ float4 ps[256];
    int bh = blockIdx.x;
    int t = threadIdx.x;               // 256
    int d4 = t & 15, part = t >> 4;    // 16 parts x 128 rows
    const float4* Vb = (const float4*)(V + (size_t)bh * Lq * Dq);
    float4 s = make_float4(0.f, 0.f, 0.f, 0.f);
    int k0 = part * 128;
    for (int k = k0; k < k0 + 128; k++) {
        float4 v = Vb[(size_t)k * 16 + d4];
        s.x += v.x; s.y += v.y; s.z += v.z; s.w += v.w;
    }
    ps[t] = s;
    __syncthreads();
    if (t < 16) {
        float4 a = ps[t];
        #pragma unroll
        for (int pI = 1; pI < 16; pI++) {
            float4 v = ps[pI * 16 + t];
            a.x += v.x; a.y += v.y; a.z += v.z; a.w += v.w;
        }
        const float inv = 1.0f / (float)Lq;
        a.x *= inv; a.y *= inv; a.z *= inv; a.w *= inv;
        ((float4*)g_vmean)[bh * 16 + t] = a;
    }
}

// ---------------- kernel 4: broadcast V_mean (wide grid) -----------------
__global__ void k_fill(float4* __restrict__ out4) {
    int i = blockIdx.x * 256 + threadIdx.x;  // BH*L*16 float4s
    int bh = i >> 15;
    int d4 = i & 15;
    out4[i] = ((const float4*)g_vmean)[bh * 16 + d4];
}

// ---------------- kernel 5: scores = (Q_top @ K^T) * scale ---------------
// 128-key tile, 256 threads, 8 warps x 5 queries; lane owns 4 contiguous
// keys (LDS.128 K loads). grid BH*16 = 512 blocks.
__global__ void k_scores(const float* __restrict__ Q, const float* __restrict__ K) {
    __shared__ float qs[NT * Dq];           // 10 KB
    __shared__ float Kt[Dq * 132];          // transposed [d][k], pad 132
    int bh = blockIdx.x >> 4;
    int kt = blockIdx.x & 15;
    int t = threadIdx.x;                    // 256
    const float* Qb = Q + (size_t)bh * Lq * Dq;
    const float* Kb = K + (size_t)bh * Lq * Dq;
    for (int j = t; j < NT * Dq; j += 256) {
        int u = j >> 6, d = j & 63;
        int qi = __ldg(&g_top[bh * NT + u]);
        qs[j] = Qb[(size_t)qi * Dq + d];
    }
    for (int j = t; j < 128 * Dq; j += 256) {
        int r = j >> 6, d = j & 63;
        Kt[d * 132 + r] = Kb[(size_t)(kt * 128 + r) * Dq + d];
    }
    __syncthreads();
    int w = t >> 5, lane = t & 31;          // warp w: queries w*5..w*5+4
    float acc[5][4] = {};
    #pragma unroll
    for (int dc = 0; dc < Dq; dc += 4) {
        float4 a[5];
        #pragma unroll
        for (int i = 0; i < 5; i++)
            a[i] = *(const float4*)&qs[(w * 5 + i) * Dq + dc];
        #pragma unroll
        for (int j = 0; j < 4; j++) {
            float4 b = *(const float4*)&Kt[(dc + j) * 132 + lane * 4];
            #pragma unroll
            for (int i = 0; i < 5; i++) {
                float aj = (j == 0) ? a[i].x : (j == 1) ? a[i].y : (j == 2) ? a[i].z : a[i].w;
                acc[i][0] = fmaf(aj, b.x, acc[i][0]);
                acc[i][1] = fmaf(aj, b.y, acc[i][1]);
                acc[i][2] = fmaf(aj, b.z, acc[i][2]);
                acc[i][3] = fmaf(aj, b.w, acc[i][3]);
            }
        }
    }
    #pragma unroll
    for (int i = 0; i < 5; i++) {
        int u = w * 5 + i;
        float4 r;
        r.x = acc[i][0] * SCALE; r.y = acc[i][1] * SCALE;
        r.z = acc[i][2] * SCALE; r.w = acc[i][3] * SCALE;
        *(float4*)&g_scores[((size_t)(bh * NT + u)) * Lq + kt * 128 + lane * 4] = r;
    }
}

// ---------------- kernel 6: softmax 2-pass, float4 + FMA-pipe exp --------
__global__ void k_softmax() {
    __shared__ float red[8];
    int row = blockIdx.x;                  // BH*NT = 1280 rows
    float4* s4 = (float4*)(g_scores + (size_t)row * Lq);
    int t = threadIdx.x, lane = t & 31, wid = t >> 5;
    float4 v0 = s4[t * 2], v1 = s4[t * 2 + 1];
    float mx = fmaxf(fmaxf(fmaxf(v0.x, v0.y), fmaxf(v0.z, v0.w)),
                     fmaxf(fmaxf(v1.x, v1.y), fmaxf(v1.z, v1.w)));
    #pragma unroll
    for (int o = 16; o; o >>= 1) mx = fmaxf(mx, __shfl_xor_sync(0xffffffffu, mx, o));
    if (lane == 0) red[wid] = mx;
    __syncthreads();
    mx = red[0];
    #pragma unroll
    for (int i = 1; i < 8; i++) mx = fmaxf(mx, red[i]);
    v0.x = fexpf(v0.x - mx); v0.y = fexpf(v0.y - mx);
    v0.z = fexpf(v0.z - mx); v0.w = fexpf(v0.w - mx);
    v1.x = fexpf(v1.x - mx); v1.y = fexpf(v1.y - mx);
    v1.z = fexpf(v1.z - mx); v1.w = fexpf(v1.w - mx);
    s4[t * 2] = v0; s4[t * 2 + 1] = v1;
    float sum = (v0.x + v0.y + v0.z + v0.w) + (v1.x + v1.y + v1.z + v1.w);
    #pragma unroll
    for (int o = 16; o; o >>= 1) sum += __shfl_xor_sync(0xffffffffu, sum, o);
    __syncthreads();
    if (lane == 0) red[wid] = sum;
    __syncthreads();
    if (t == 0) {
        sum = 0.f;
        #pragma unroll
        for (int i = 0; i < 8; i++) sum += red[i];
        g_inv[row] = 1.0f / sum;
    }
}

// ---------------- kernel 7: ctx partial = exp_scores @ V (k-split) -------
__global__ void k_ctx(const float* __restrict__ V) {
    __shared__ float Vs[128 * Dq];          // 32 KB
    int bh = blockIdx.x >> 3;
    int ks = blockIdx.x & 7;
    int t = threadIdx.x;
    int tu = t >> 5;
    int td = t & 31;
    const float* Vb = V + (size_t)bh * Lq * Dq;
    const float* Sb = g_scores + (size_t)bh * NT * Lq;
    float acc[5][2] = {};
    for (int sub = 0; sub < 2; sub++) {
        int k0 = ks * 256 + sub * 128;
        __syncthreads();
        for (int j = t; j < 128 * Dq; j += 256) Vs[j] = Vb[(size_t)k0 * Dq + j];
        __syncthreads();
        #pragma unroll 2
        for (int kk = 0; kk < 128; kk += 4) {
            float4 a[5];
            #pragma unroll
            for (int i = 0; i < 5; i++)
                a[i] = *(const float4*)&Sb[(size_t)(tu * 5 + i) * Lq + k0 + kk];
            #pragma unroll
            for (int j = 0; j < 4; j++) {
                float2 v = *(const float2*)&Vs[(kk + j) * Dq + td * 2];
                #pragma unroll
                for (int i = 0; i < 5; i++) {
                    float aj = (j == 0) ? a[i].x : (j == 1) ? a[i].y : (j == 2) ? a[i].z : a[i].w;
                    acc[i][0] = fmaf(aj, v.x, acc[i][0]);
                    acc[i][1] = fmaf(aj, v.y, acc[i][1]);
                }
            }
        }
    }
    #pragma unroll
    for (int i = 0; i < 5; i++) {
        int u = tu * 5 + i;
        float2 r; r.x = acc[i][0]; r.y = acc[i][1];
        *(float2*)&g_part[(((size_t)ks * BH + bh) * NT + u) * Dq + td * 2] = r;
    }
}

// ---------------- kernel 8: sum partials * inv_sum, scatter --------------
__global__ void k_scatter(float* __restrict__ out) {
    int i = blockIdx.x * blockDim.x + threadIdx.x;   // BH*NT*D = 81920
    if (i >= BH * NT * Dq) return;
    int d = i & 63;
    int u = (i >> 6) % NT;
    int bh = (i >> 6) / NT;
    float s = 0.f;
    #pragma unroll
    for (int ks = 0; ks < 8; ks++)
        s += g_part[(((size_t)ks * BH + bh) * NT + u) * Dq + d];
    s *= g_inv[bh * NT + u];
    int qi = g_top[bh * NT + u];
    out[((size_t)bh * Lq + qi) * Dq + d] = s;
}

// ---------------- launch ---------------------------------------------------
extern "C" void kernel_launch(void* const* d_in, const int* in_sizes, int n_in,
                              void* d_out, int out_size) {
    const float* Q = (const float*)d_in[0];
    const float* K = (const float*)d_in[1];
    const float* V = (const float*)d_in[2];
    const int* idxs = (const int*)d_in[3];
    float* out = (float*)d_out;

    // order: k_scores (4-key/lane version) is user launch #4 (profiled).
    k_vmean<<<BH, 256>>>(V);                                  // 1
    k_M<<<(BH * Lq) / 8, 256>>>(Q, K, idxs);                  // 2
    k_topk<<<BH, 256>>>();                                    // 3
    k_scores<<<BH * 16, 256>>>(Q, K);                         // 4  <-- profiled
    k_fill<<<(BH * Lq * Dq / 4) / 256, 256>>>((float4*)out);  // 5
    k_softmax<<<BH * NT, 256>>>();                            // 6
    k_ctx<<<BH * 8, 256>>>(V);                                // 7
    k_scatter<<<(BH * NT * Dq + 255) / 256, 256>>>(out);      // 8
}

// round 12
// speedup vs baseline: 1.5254x; 1.0045x over previous
#include <cuda_runtime.h>
#include <cuda_bf16.h>
#include <math_constants.h>

// Problem constants (fixed by setup_inputs)
#define Bq 4
#define Hq 8
#define BH 32          // B*H
#define Lq 2048
#define Dq 64
#define SK 40          // sample_k
#define NT 40          // n_top
#define NS 32          // key splits in flash kernel (64 keys each)
#define SCALE 0.125f   // 1/sqrt(64)

// ---------------- scratch (device globals; no allocation) ----------------
__device__ float g_M[BH * Lq];                 // 256 KB
__device__ int   g_top[BH * NT];               // 5 KB
__device__ float g_vmean[BH * Dq];             // 8 KB
__device__ float g_pm[NS * BH * NT];           // per-split row max
__device__ float g_psum[NS * BH * NT];         // per-split exp-sum
__device__ float g_part[(size_t)NS * BH * NT * Dq];  // 10.5 MB partial ctx

// Fast exp on the FMA pipe: exp(x) = 2^(x*log2e), deg-6 poly + exponent bits.
__device__ __forceinline__ float fexpf(float x) {
    float y = x * 1.4426950408889634f;
    y = fmaxf(y, -125.0f);
    float r = rintf(y);
    float f = y - r;
    float p = 1.5403530e-4f;
    p = fmaf(p, f, 1.3333558e-3f);
    p = fmaf(p, f, 9.6181291e-3f);
    p = fmaf(p, f, 5.5504109e-2f);
    p = fmaf(p, f, 2.4022651e-1f);
    p = fmaf(p, f, 6.9314718e-1f);
    p = fmaf(p, f, 1.0f);
    return p * __int_as_float(((int)r + 127) << 23);
}

// ---------------- kernel 1: M[bh,l] = max_s q.k - sum_s/L ----------------
template<int O, int V>
__device__ __forceinline__ void fold(float* p, int lane) {
    bool hi = (lane & O) != 0;
    #pragma unroll
    for (int j = 0; j < V / 2; j++) {
        float send = hi ? p[j] : p[j + V / 2];
        float keep = hi ? p[j + V / 2] : p[j];
        p[j] = keep + __shfl_xor_sync(0xffffffffu, send, O);
    }
}

__device__ __forceinline__ float dot16(const float* __restrict__ Kb, float2 q,
                                       int e, int base, int lane) {
    float p[16];
    #pragma unroll
    for (int j = 0; j < 16; j++) {
        int idx = __shfl_sync(0xffffffffu, e, base + j);
        float2 k = ((const float2*)(Kb + (size_t)idx * Dq))[lane];
        p[j] = q.x * k.x + q.y * k.y;
    }
    fold<16, 16>(p, lane);
    fold<8, 8>(p, lane);
    fold<4, 4>(p, lane);
    fold<2, 2>(p, lane);
    p[0] += __shfl_xor_sync(0xffffffffu, p[0], 1);
    return p[0];
}

__device__ __forceinline__ float dot8(const float* __restrict__ Kb, float2 q,
                                      int e, int lane) {
    float p[8];
    #pragma unroll
    for (int j = 0; j < 8; j++) {
        int idx = __shfl_sync(0xffffffffu, e, j);
        float2 k = ((const float2*)(Kb + (size_t)idx * Dq))[lane];
        p[j] = q.x * k.x + q.y * k.y;
    }
    fold<16, 8>(p, lane);
    fold<8, 4>(p, lane);
    fold<4, 2>(p, lane);
    p[0] += __shfl_xor_sync(0xffffffffu, p[0], 2);
    p[0] += __shfl_xor_sync(0xffffffffu, p[0], 1);
    return p[0];
}

__global__ void k_M(const float* __restrict__ Q, const float* __restrict__ K,
                    const int* __restrict__ idxs) {
    int w = blockIdx.x * 8 + (threadIdx.x >> 5);   // query id (bh*2048 + l)
    int lane = threadIdx.x & 31;
    int bh = w >> 11;
    int l  = w & (Lq - 1);
    float2 q = ((const float2*)(Q + (size_t)w * Dq))[lane];
    const float* Kb = K + (size_t)bh * Lq * Dq;
    int e0 = idxs[l * SK + lane];
    int e1 = (lane < 8) ? idxs[l * SK + 32 + lane] : 0;

    float a = dot16(Kb, q, e0, 0, lane);
    float b = dot16(Kb, q, e0, 16, lane);
    float c = dot8(Kb, q, e1, lane);

    float mx = fmaxf(fmaxf(a, b), c);
    float sm = 0.5f * (a + b) + 0.25f * c;
    #pragma unroll
    for (int o = 16; o; o >>= 1) {
        mx = fmaxf(mx, __shfl_xor_sync(0xffffffffu, mx, o));
        sm += __shfl_xor_sync(0xffffffffu, sm, o);
    }
    if (lane == 0) g_M[w] = mx - sm * (1.0f / (float)Lq);
}

// ---------------- kernel 2: top-40 per (b,h), 4-level radix select -------
__global__ void k_topk() {
    __shared__ int hist[8][256];
    __shared__ int suf[257];
    __shared__ int wred[8];
    __shared__ int s_T, s_cnt, s_min;
    int bh = blockIdx.x;
    int t = threadIdx.x, lane = t & 31, w = t >> 5;

    unsigned key[8];
    #pragma unroll
    for (int j = 0; j < 8; j++) {
        unsigned u = __float_as_uint(g_M[bh * Lq + t * 8 + j]);
        key[j] = (u & 0x80000000u) ? ~u : (u | 0x80000000u);
    }
    unsigned prefix = 0;
    int need = NT;
    if (t == 0) s_cnt = 0;

    #pragma unroll
    for (int level = 0; level < 4; level++) {
        int shift = 24 - 8 * level;
        for (int b = t; b < 8 * 256; b += 256) (&hist[0][0])[b] = 0;
        __syncthreads();
        #pragma unroll
        for (int j = 0; j < 8; j++) {
            bool match = (level == 0) || ((key[j] >> (shift + 8)) == prefix);
            if (match) atomicAdd(&hist[w][(key[j] >> shift) & 255u], 1);
        }
        __syncthreads();
        int h = 0;
        #pragma unroll
        for (int ww = 0; ww < 8; ww++) h += hist[ww][t];
        int sv = h;
        #pragma unroll
        for (int off = 1; off < 32; off <<= 1) {
            int v = __shfl_down_sync(0xffffffffu, sv, off);
            if (lane + off < 32) sv += v;
        }
        int wtot = __shfl_sync(0xffffffffu, sv, 0);
        if (lane == 0) wred[w] = wtot;
        __syncthreads();
        int higher = 0;
        #pragma unroll
        for (int ww = 0; ww < 8; ww++) if (ww > w) higher += wred[ww];
        suf[t] = sv + higher;
        if (t == 0) suf[256] = 0;
        __syncthreads();
        if (suf[t] >= need && suf[t + 1] < need) s_T = t;
        __syncthreads();
        int T = s_T;
        #pragma unroll
        for (int j = 0; j < 8; j++) {
            bool match = (level == 0) || ((key[j] >> (shift + 8)) == prefix);
            if (match && (int)((key[j] >> shift) & 255u) > T) {
                int p = atomicAdd(&s_cnt, 1);
                g_top[bh * NT + p] = t * 8 + j;
            }
        }
        need -= suf[T + 1];
        prefix = (prefix << 8) | (unsigned)T;
        __syncthreads();
    }

    for (int it = 0; it < need; it++) {
        int mi = Lq;
        #pragma unroll
        for (int j = 0; j < 8; j++)
            if (key[j] == prefix) mi = min(mi, t * 8 + j);
        #pragma unroll
        for (int off = 16; off; off >>= 1)
            mi = min(mi, __shfl_xor_sync(0xffffffffu, mi, off));
        if (lane == 0) wred[w] = mi;
        __syncthreads();
        if (t == 0) {
            int m = wred[0];
            #pragma unroll
            for (int ww = 1; ww < 8; ww++) m = min(m, wred[ww]);
            s_min = m;
            g_top[bh * NT + (NT - need) + it] = m;
        }
        __syncthreads();
        int m = s_min;
        if (m >= t * 8 && m < t * 8 + 8) key[m - t * 8] = 0u;
        __syncthreads();
    }
}

// ---------------- kernel 3: V mean over L per (b,h), float4 --------------
__global__ void k_vmean(const float* __restrict__ V) {
    __shared__ float4 ps[256];
    int bh = blockIdx.x;
    int t = threadIdx.x;
    int d4 = t & 15, part = t >> 4;
    const float4* Vb = (const float4*)(V + (size_t)bh * Lq * Dq);
    float4 s = make_float4(0.f, 0.f, 0.f, 0.f);
    int k0 = part * 128;
    for (int k = k0; k < k0 + 128; k++) {
        float4 v = Vb[(size_t)k * 16 + d4];
        s.x += v.x; s.y += v.y; s.z += v.z; s.w += v.w;
    }
    ps[t] = s;
    __syncthreads();
    if (t < 16) {
        float4 a = ps[t];
        #pragma unroll
        for (int pI = 1; pI < 16; pI++) {
            float4 v = ps[pI * 16 + t];
            a.x += v.x; a.y += v.y; a.z += v.z; a.w += v.w;
        }
        const float inv = 1.0f / (float)Lq;
        a.x *= inv; a.y *= inv; a.z *= inv; a.w *= inv;
        ((float4*)g_vmean)[bh * 16 + t] = a;
    }
}

// ---------------- kernel 4: broadcast V_mean (wide grid) -----------------
__global__ void k_fill(float4* __restrict__ out4) {
    int i = blockIdx.x * 256 + threadIdx.x;
    int bh = i >> 15;
    int d4 = i & 15;
    out4[i] = ((const float4*)g_vmean)[bh * 16 + d4];
}

// ---------------- kernel 5: fused flash attention over 64-key split ------
// grid = BH * NS = 1024 blocks, 256 threads. Per block:
//   S = Q_top @ K_tile^T (40x64), row-local max/expsum, P = exp(S-m),
//   ctx_part = P @ V_tile (40x64). Partials combined in k_comb.
__global__ void k_flash(const float* __restrict__ Q,
                        const float* __restrict__ K,
                        const float* __restrict__ V) {
    __shared__ float qs[NT * Dq];      // 10 KB
    __shared__ float Kt[Dq * 68];      // 17 KB, transposed [d][k]; reused as P
    __shared__ float Vs[64 * Dq];      // 16 KB
    int bh = blockIdx.x >> 5;
    int ks = blockIdx.x & 31;
    int t = threadIdx.x;               // 256
    const float* Qb = Q + (size_t)bh * Lq * Dq;
    const float* Kb = K + (size_t)bh * Lq * Dq;
    const float* Vb = V + (size_t)bh * Lq * Dq;
    for (int j = t; j < NT * Dq; j += 256) {
        int u = j >> 6, d = j & 63;
        int qi = __ldg(&g_top[bh * NT + u]);
        qs[j] = Qb[(size_t)qi * Dq + d];
    }
    for (int j = t; j < 64 * Dq; j += 256) {
        int r = j >> 6, d = j & 63;
        Kt[d * 68 + r] = Kb[(size_t)(ks * 64 + r) * Dq + d];
    }
    for (int j = t; j < 64 * Dq; j += 256) Vs[j] = Vb[(size_t)ks * 64 * Dq + j];
    __syncthreads();

    int w = t >> 5, lane = t & 31;     // warp w: queries w*5..w*5+4; lane: 2 keys
    float acc[5][2] = {};
    #pragma unroll
    for (int dc = 0; dc < Dq; dc += 4) {
        float4 a[5];
        #pragma unroll
        for (int i = 0; i < 5; i++)
            a[i] = *(const float4*)&qs[(w * 5 + i) * Dq + dc];
        #pragma unroll
        for (int j = 0; j < 4; j++) {
            float2 b = *(const float2*)&Kt[(dc + j) * 68 + lane * 2];
            #pragma unroll
            for (int i = 0; i < 5; i++) {
                float aj = (j == 0) ? a[i].x : (j == 1) ? a[i].y : (j == 2) ? a[i].z : a[i].w;
                acc[i][0] = fmaf(aj, b.x, acc[i][0]);
                acc[i][1] = fmaf(aj, b.y, acc[i][1]);
            }
        }
    }
    // per-row stats + exp (P kept in registers)
    int sb = (bh * NS + ks) * NT + w * 5;
    #pragma unroll
    for (int i = 0; i < 5; i++) {
        acc[i][0] *= SCALE; acc[i][1] *= SCALE;
        float mi = fmaxf(acc[i][0], acc[i][1]);
        #pragma unroll
        for (int o = 16; o; o >>= 1) mi = fmaxf(mi, __shfl_xor_sync(0xffffffffu, mi, o));
        float e0 = fexpf(acc[i][0] - mi);
        float e1 = fexpf(acc[i][1] - mi);
        acc[i][0] = e0; acc[i][1] = e1;
        float s = e0 + e1;
        #pragma unroll
        for (int o = 16; o; o >>= 1) s += __shfl_xor_sync(0xffffffffu, s, o);
        if (lane == 0) { g_pm[sb + i] = mi; g_psum[sb + i] = s; }
    }
    __syncthreads();                    // all warps done reading Kt
    float* P = Kt;                      // reuse: 40*64 floats fit in Kt
    #pragma unroll
    for (int i = 0; i < 5; i++)
        *(float2*)&P[(w * 5 + i) * 64 + lane * 2] = make_float2(acc[i][0], acc[i][1]);
    __syncthreads();

    // GEMM2: ctx_part[u][d] = sum_k P[u][k] * Vs[k][d]; lane owns 2 d's
    float acc2[5][2] = {};
    #pragma unroll 4
    for (int kk = 0; kk < 64; kk += 4) {
        float4 a[5];
        #pragma unroll
        for (int i = 0; i < 5; i++)
            a[i] = *(const float4*)&P[(w * 5 + i) * 64 + kk];
        #pragma unroll
        for (int j = 0; j < 4; j++) {
            float2 v = *(const float2*)&Vs[(kk + j) * Dq + lane * 2];
            #pragma unroll
            for (int i = 0; i < 5; i++) {
                float aj = (j == 0) ? a[i].x : (j == 1) ? a[i].y : (j == 2) ? a[i].z : a[i].w;
                acc2[i][0] = fmaf(aj, v.x, acc2[i][0]);
                acc2[i][1] = fmaf(aj, v.y, acc2[i][1]);
            }
        }
    }
    #pragma unroll
    for (int i = 0; i < 5; i++) {
        float2 r; r.x = acc2[i][0]; r.y = acc2[i][1];
        *(float2*)&g_part[((size_t)(ks * BH + bh) * NT + w * 5 + i) * Dq + lane * 2] = r;
    }
}

// ---------------- kernel 6: combine splits + scatter ---------------------
__global__ void k_comb(float* __restrict__ out) {
    int i = blockIdx.x * 256 + threadIdx.x;   // BH*NT*Dq = 81920
    if (i >= BH * NT * Dq) return;
    int d = i & 63;
    int r = i >> 6;
    int u = r % NT;
    int bh = r / NT;
    float M = -CUDART_INF_F;
    #pragma unroll 8
    for (int s = 0; s < NS; s++)
        M = fmaxf(M, g_pm[(bh * NS + s) * NT + u]);
    float sum = 0.f, ctx = 0.f;
    #pragma unroll 4
    for (int s = 0; s < NS; s++) {
        float wgt = fexpf(g_pm[(bh * NS + s) * NT + u] - M);
        sum = fmaf(g_psum[(bh * NS + s) * NT + u], wgt, sum);
        ctx = fmaf(g_part[((size_t)(s * BH + bh) * NT + u) * Dq + d], wgt, ctx);
    }
    int qi = g_top[bh * NT + u];
    out[((size_t)bh * Lq + qi) * Dq + d] = ctx / sum;
}

// ---------------- launch ---------------------------------------------------
extern "C" void kernel_launch(void* const* d_in, const int* in_sizes, int n_in,
                              void* d_out, int out_size) {
    const float* Q = (const float*)d_in[0];
    const float* K = (const float*)d_in[1];
    const float* V = (const float*)d_in[2];
    const int* idxs = (const int*)d_in[3];
    float* out = (float*)d_out;

    // order: k_flash is user launch #4 (profiled).
    k_vmean<<<BH, 256>>>(V);                                  // 1
    k_M<<<(BH * Lq) / 8, 256>>>(Q, K, idxs);                  // 2
    k_topk<<<BH, 256>>>();                                    // 3
    k_flash<<<BH * NS, 256>>>(Q, K, V);                       // 4  <-- profiled
    k_fill<<<(BH * Lq * Dq / 4) / 256, 256>>>((float4*)out);  // 5
    k_comb<<<(BH * NT * Dq + 255) / 256, 256>>>(out);         // 6
}

// round 13
// speedup vs baseline: 1.5457x; 1.0133x over previous
#include <cuda_runtime.h>
#include <cuda_bf16.h>
#include <math_constants.h>

// Problem constants (fixed by setup_inputs)
#define Bq 4
#define Hq 8
#define BH 32          // B*H
#define Lq 2048
#define Dq 64
#define SK 40          // sample_k
#define NT 40          // n_top
#define NS 32          // key splits in flash kernel (64 keys each)
#define SCALE 0.125f   // 1/sqrt(64)

// ---------------- scratch (device globals; no allocation) ----------------
__device__ float g_M[BH * Lq];                 // 256 KB
__device__ int   g_top[BH * NT];               // 5 KB
__device__ float g_vmean[BH * Dq];             // 8 KB
__device__ float g_pm[NS * BH * NT];           // per-split row max
__device__ float g_psum[NS * BH * NT];         // per-split exp-sum
__device__ float g_part[(size_t)NS * BH * NT * Dq];  // 10.5 MB partial ctx

// Fast exp on the FMA pipe: exp(x) = 2^(x*log2e), deg-6 poly + exponent bits.
__device__ __forceinline__ float fexpf(float x) {
    float y = x * 1.4426950408889634f;
    y = fmaxf(y, -125.0f);
    float r = rintf(y);
    float f = y - r;
    float p = 1.5403530e-4f;
    p = fmaf(p, f, 1.3333558e-3f);
    p = fmaf(p, f, 9.6181291e-3f);
    p = fmaf(p, f, 5.5504109e-2f);
    p = fmaf(p, f, 2.4022651e-1f);
    p = fmaf(p, f, 6.9314718e-1f);
    p = fmaf(p, f, 1.0f);
    return p * __int_as_float(((int)r + 127) << 23);
}

// ---------------- kernel 1: M[bh,l] = max_s q.k - sum_s/L ----------------
template<int O, int V>
__device__ __forceinline__ void fold(float* p, int lane) {
    bool hi = (lane & O) != 0;
    #pragma unroll
    for (int j = 0; j < V / 2; j++) {
        float send = hi ? p[j] : p[j + V / 2];
        float keep = hi ? p[j + V / 2] : p[j];
        p[j] = keep + __shfl_xor_sync(0xffffffffu, send, O);
    }
}

__device__ __forceinline__ float dot16(const float* __restrict__ Kb, float2 q,
                                       int e, int base, int lane) {
    float p[16];
    #pragma unroll
    for (int j = 0; j < 16; j++) {
        int idx = __shfl_sync(0xffffffffu, e, base + j);
        float2 k = ((const float2*)(Kb + (size_t)idx * Dq))[lane];
        p[j] = q.x * k.x + q.y * k.y;
    }
    fold<16, 16>(p, lane);
    fold<8, 8>(p, lane);
    fold<4, 4>(p, lane);
    fold<2, 2>(p, lane);
    p[0] += __shfl_xor_sync(0xffffffffu, p[0], 1);
    return p[0];
}

__device__ __forceinline__ float dot8(const float* __restrict__ Kb, float2 q,
                                      int e, int lane) {
    float p[8];
    #pragma unroll
    for (int j = 0; j < 8; j++) {
        int idx = __shfl_sync(0xffffffffu, e, j);
        float2 k = ((const float2*)(Kb + (size_t)idx * Dq))[lane];
        p[j] = q.x * k.x + q.y * k.y;
    }
    fold<16, 8>(p, lane);
    fold<8, 4>(p, lane);
    fold<4, 2>(p, lane);
    p[0] += __shfl_xor_sync(0xffffffffu, p[0], 2);
    p[0] += __shfl_xor_sync(0xffffffffu, p[0], 1);
    return p[0];
}

__global__ void k_M(const float* __restrict__ Q, const float* __restrict__ K,
                    const int* __restrict__ idxs) {
    int w = blockIdx.x * 8 + (threadIdx.x >> 5);   // query id (bh*2048 + l)
    int lane = threadIdx.x & 31;
    int bh = w >> 11;
    int l  = w & (Lq - 1);
    float2 q = ((const float2*)(Q + (size_t)w * Dq))[lane];
    const float* Kb = K + (size_t)bh * Lq * Dq;
    int e0 = idxs[l * SK + lane];
    int e1 = (lane < 8) ? idxs[l * SK + 32 + lane] : 0;

    float a = dot16(Kb, q, e0, 0, lane);
    float b = dot16(Kb, q, e0, 16, lane);
    float c = dot8(Kb, q, e1, lane);

    float mx = fmaxf(fmaxf(a, b), c);
    float sm = 0.5f * (a + b) + 0.25f * c;
    #pragma unroll
    for (int o = 16; o; o >>= 1) {
        mx = fmaxf(mx, __shfl_xor_sync(0xffffffffu, mx, o));
        sm += __shfl_xor_sync(0xffffffffu, sm, o);
    }
    if (lane == 0) g_M[w] = mx - sm * (1.0f / (float)Lq);
}

// ---------------- kernel 2: top-40 per (b,h), 4-level radix select -------
__global__ void k_topk() {
    __shared__ int hist[8][256];
    __shared__ int suf[257];
    __shared__ int wred[8];
    __shared__ int s_T, s_cnt, s_min;
    int bh = blockIdx.x;
    int t = threadIdx.x, lane = t & 31, w = t >> 5;

    unsigned key[8];
    #pragma unroll
    for (int j = 0; j < 8; j++) {
        unsigned u = __float_as_uint(g_M[bh * Lq + t * 8 + j]);
        key[j] = (u & 0x80000000u) ? ~u : (u | 0x80000000u);
    }
    unsigned prefix = 0;
    int need = NT;
    if (t == 0) s_cnt = 0;

    #pragma unroll
    for (int level = 0; level < 4; level++) {
        int shift = 24 - 8 * level;
        for (int b = t; b < 8 * 256; b += 256) (&hist[0][0])[b] = 0;
        __syncthreads();
        #pragma unroll
        for (int j = 0; j < 8; j++) {
            bool match = (level == 0) || ((key[j] >> (shift + 8)) == prefix);
            if (match) atomicAdd(&hist[w][(key[j] >> shift) & 255u], 1);
        }
        __syncthreads();
        int h = 0;
        #pragma unroll
        for (int ww = 0; ww < 8; ww++) h += hist[ww][t];
        int sv = h;
        #pragma unroll
        for (int off = 1; off < 32; off <<= 1) {
            int v = __shfl_down_sync(0xffffffffu, sv, off);
            if (lane + off < 32) sv += v;
        }
        int wtot = __shfl_sync(0xffffffffu, sv, 0);
        if (lane == 0) wred[w] = wtot;
        __syncthreads();
        int higher = 0;
        #pragma unroll
        for (int ww = 0; ww < 8; ww++) if (ww > w) higher += wred[ww];
        suf[t] = sv + higher;
        if (t == 0) suf[256] = 0;
        __syncthreads();
        if (suf[t] >= need && suf[t + 1] < need) s_T = t;
        __syncthreads();
        int T = s_T;
        #pragma unroll
        for (int j = 0; j < 8; j++) {
            bool match = (level == 0) || ((key[j] >> (shift + 8)) == prefix);
            if (match && (int)((key[j] >> shift) & 255u) > T) {
                int p = atomicAdd(&s_cnt, 1);
                g_top[bh * NT + p] = t * 8 + j;
            }
        }
        need -= suf[T + 1];
        prefix = (prefix << 8) | (unsigned)T;
        __syncthreads();
    }

    for (int it = 0; it < need; it++) {
        int mi = Lq;
        #pragma unroll
        for (int j = 0; j < 8; j++)
            if (key[j] == prefix) mi = min(mi, t * 8 + j);
        #pragma unroll
        for (int off = 16; off; off >>= 1)
            mi = min(mi, __shfl_xor_sync(0xffffffffu, mi, off));
        if (lane == 0) wred[w] = mi;
        __syncthreads();
        if (t == 0) {
            int m = wred[0];
            #pragma unroll
            for (int ww = 1; ww < 8; ww++) m = min(m, wred[ww]);
            s_min = m;
            g_top[bh * NT + (NT - need) + it] = m;
        }
        __syncthreads();
        int m = s_min;
        if (m >= t * 8 && m < t * 8 + 8) key[m - t * 8] = 0u;
        __syncthreads();
    }
}

// ---------------- kernel 3: V mean over L per (b,h), float4 --------------
__global__ void k_vmean(const float* __restrict__ V) {
    __shared__ float4 ps[256];
    int bh = blockIdx.x;
    int t = threadIdx.x;
    int d4 = t & 15, part = t >> 4;
    const float4* Vb = (const float4*)(V + (size_t)bh * Lq * Dq);
    float4 s = make_float4(0.f, 0.f, 0.f, 0.f);
    int k0 = part * 128;
    for (int k = k0; k < k0 + 128; k++) {
        float4 v = Vb[(size_t)k * 16 + d4];
        s.x += v.x; s.y += v.y; s.z += v.z; s.w += v.w;
    }
    ps[t] = s;
    __syncthreads();
    if (t < 16) {
        float4 a = ps[t];
        #pragma unroll
        for (int pI = 1; pI < 16; pI++) {
            float4 v = ps[pI * 16 + t];
            a.x += v.x; a.y += v.y; a.z += v.z; a.w += v.w;
        }
        const float inv = 1.0f / (float)Lq;
        a.x *= inv; a.y *= inv; a.z *= inv; a.w *= inv;
        ((float4*)g_vmean)[bh * 16 + t] = a;
    }
}

// ---------------- kernel 4: broadcast V_mean (wide grid) -----------------
__global__ void k_fill(float4* __restrict__ out4) {
    int i = blockIdx.x * 256 + threadIdx.x;
    int bh = i >> 15;
    int d4 = i & 15;
    out4[i] = ((const float4*)g_vmean)[bh * 16 + d4];
}

// ---------------- kernel 5: fused flash attention over 64-key split ------
// grid = BH * NS = 1024 blocks, 256 threads, launch_bounds(256,4) so ptxas
// can pipeline the smem loads. Double-buffered K/V chunk loads in both GEMMs.
__global__ void __launch_bounds__(256, 4)
k_flash(const float* __restrict__ Q,
        const float* __restrict__ K,
        const float* __restrict__ V) {
    __shared__ float qs[NT * Dq];      // 10 KB
    __shared__ float Kt[Dq * 66];      // 16.5 KB transposed [d][k]; reused as P
    __shared__ float Vs[64 * Dq];      // 16 KB
    __shared__ int stop[NT];
    int bh = blockIdx.x >> 5;
    int ks = blockIdx.x & 31;
    int t = threadIdx.x;               // 256
    const float* Qb = Q + (size_t)bh * Lq * Dq;
    const float* Kb = K + (size_t)bh * Lq * Dq;
    const float* Vb = V + (size_t)bh * Lq * Dq;
    if (t < NT) stop[t] = g_top[bh * NT + t];
    __syncthreads();
    for (int j = t; j < NT * Dq; j += 256) {
        int u = j >> 6, d = j & 63;
        qs[j] = Qb[(size_t)stop[u] * Dq + d];
    }
    for (int j = t; j < 64 * Dq; j += 256) {
        int r = j >> 6, d = j & 63;
        Kt[d * 66 + r] = Kb[(size_t)(ks * 64 + r) * Dq + d];
    }
    for (int j = t; j < 64 * Dq; j += 256) Vs[j] = Vb[(size_t)ks * 64 * Dq + j];
    __syncthreads();

    int w = t >> 5, lane = t & 31;     // warp w: queries w*5..w*5+4; lane: 2 keys
    float acc0[5] = {}, acc1[5] = {};
    // GEMM1, double-buffered over 4-d chunks
    float2 b0 = *(const float2*)&Kt[0 * 66 + lane * 2];
    float2 b1 = *(const float2*)&Kt[1 * 66 + lane * 2];
    float2 b2 = *(const float2*)&Kt[2 * 66 + lane * 2];
    float2 b3 = *(const float2*)&Kt[3 * 66 + lane * 2];
    #pragma unroll
    for (int dc = 0; dc < Dq; dc += 4) {
        float4 a[5];
        #pragma unroll
        for (int i = 0; i < 5; i++)
            a[i] = *(const float4*)&qs[(w * 5 + i) * Dq + dc];
        float2 n0, n1, n2, n3;
        if (dc + 4 < Dq) {
            n0 = *(const float2*)&Kt[(dc + 4) * 66 + lane * 2];
            n1 = *(const float2*)&Kt[(dc + 5) * 66 + lane * 2];
            n2 = *(const float2*)&Kt[(dc + 6) * 66 + lane * 2];
            n3 = *(const float2*)&Kt[(dc + 7) * 66 + lane * 2];
        }
        #pragma unroll
        for (int i = 0; i < 5; i++) {
            acc0[i] = fmaf(a[i].x, b0.x, acc0[i]); acc1[i] = fmaf(a[i].x, b0.y, acc1[i]);
            acc0[i] = fmaf(a[i].y, b1.x, acc0[i]); acc1[i] = fmaf(a[i].y, b1.y, acc1[i]);
            acc0[i] = fmaf(a[i].z, b2.x, acc0[i]); acc1[i] = fmaf(a[i].z, b2.y, acc1[i]);
            acc0[i] = fmaf(a[i].w, b3.x, acc0[i]); acc1[i] = fmaf(a[i].w, b3.y, acc1[i]);
        }
        if (dc + 4 < Dq) { b0 = n0; b1 = n1; b2 = n2; b3 = n3; }
    }
    // per-row stats, batched butterflies (independent per row)
    float m[5], s[5];
    #pragma unroll
    for (int i = 0; i < 5; i++) {
        acc0[i] *= SCALE; acc1[i] *= SCALE;
        m[i] = fmaxf(acc0[i], acc1[i]);
    }
    #pragma unroll
    for (int o = 16; o; o >>= 1) {
        #pragma unroll
        for (int i = 0; i < 5; i++)
            m[i] = fmaxf(m[i], __shfl_xor_sync(0xffffffffu, m[i], o));
    }
    #pragma unroll
    for (int i = 0; i < 5; i++) {
        acc0[i] = fexpf(acc0[i] - m[i]);
        acc1[i] = fexpf(acc1[i] - m[i]);
        s[i] = acc0[i] + acc1[i];
    }
    #pragma unroll
    for (int o = 16; o; o >>= 1) {
        #pragma unroll
        for (int i = 0; i < 5; i++)
            s[i] += __shfl_xor_sync(0xffffffffu, s[i], o);
    }
    int sb = (bh * NS + ks) * NT + w * 5;
    if (lane == 0) {
        #pragma unroll
        for (int i = 0; i < 5; i++) { g_pm[sb + i] = m[i]; g_psum[sb + i] = s[i]; }
    }
    __syncthreads();                    // all warps done reading Kt
    float* P = Kt;                      // reuse (2560 floats fit)
    #pragma unroll
    for (int i = 0; i < 5; i++)
        *(float2*)&P[(w * 5 + i) * 64 + lane * 2] = make_float2(acc0[i], acc1[i]);
    __syncthreads();

    // GEMM2: ctx_part[u][d] = sum_k P[u][k] * Vs[k][d]; lane owns 2 d's
    float c0[5] = {}, c1[5] = {};
    float2 v0 = *(const float2*)&Vs[0 * Dq + lane * 2];
    float2 v1 = *(const float2*)&Vs[1 * Dq + lane * 2];
    float2 v2 = *(const float2*)&Vs[2 * Dq + lane * 2];
    float2 v3 = *(const float2*)&Vs[3 * Dq + lane * 2];
    #pragma unroll
    for (int kk = 0; kk < 64; kk += 4) {
        float4 a[5];
        #pragma unroll
        for (int i = 0; i < 5; i++)
            a[i] = *(const float4*)&P[(w * 5 + i) * 64 + kk];
        float2 n0, n1, n2, n3;
        if (kk + 4 < 64) {
            n0 = *(const float2*)&Vs[(kk + 4) * Dq + lane * 2];
            n1 = *(const float2*)&Vs[(kk + 5) * Dq + lane * 2];
            n2 = *(const float2*)&Vs[(kk + 6) * Dq + lane * 2];
            n3 = *(const float2*)&Vs[(kk + 7) * Dq + lane * 2];
        }
        #pragma unroll
        for (int i = 0; i < 5; i++) {
            c0[i] = fmaf(a[i].x, v0.x, c0[i]); c1[i] = fmaf(a[i].x, v0.y, c1[i]);
            c0[i] = fmaf(a[i].y, v1.x, c0[i]); c1[i] = fmaf(a[i].y, v1.y, c1[i]);
            c0[i] = fmaf(a[i].z, v2.x, c0[i]); c1[i] = fmaf(a[i].z, v2.y, c1[i]);
            c0[i] = fmaf(a[i].w, v3.x, c0[i]); c1[i] = fmaf(a[i].w, v3.y, c1[i]);
        }
        if (kk + 4 < 64) { v0 = n0; v1 = n1; v2 = n2; v3 = n3; }
    }
    #pragma unroll
    for (int i = 0; i < 5; i++)
        *(float2*)&g_part[((size_t)(ks * BH + bh) * NT + w * 5 + i) * Dq + lane * 2]
            = make_float2(c0[i], c1[i]);
}

// ---------------- kernel 6: combine splits + scatter ---------------------
__global__ void k_comb(float* __restrict__ out) {
    int i = blockIdx.x * 256 + threadIdx.x;   // BH*NT*Dq = 81920
    if (i >= BH * NT * Dq) return;
    int d = i & 63;
    int r = i >> 6;
    int u = r % NT;
    int bh = r / NT;
    float M = -CUDART_INF_F;
    #pragma unroll 8
    for (int s = 0; s < NS; s++)
        M = fmaxf(M, g_pm[(bh * NS + s) * NT + u]);
    float sum = 0.f, ctx = 0.f;
    #pragma unroll 4
    for (int s = 0; s < NS; s++) {
        float wgt = fexpf(g_pm[(bh * NS + s) * NT + u] - M);
        sum = fmaf(g_psum[(bh * NS + s) * NT + u], wgt, sum);
        ctx = fmaf(g_part[((size_t)(s * BH + bh) * NT + u) * Dq + d], wgt, ctx);
    }
    int qi = g_top[bh * NT + u];
    out[((size_t)bh * Lq + qi) * Dq + d] = ctx / sum;
}

// ---------------- launch ---------------------------------------------------
extern "C" void kernel_launch(void* const* d_in, const int* in_sizes, int n_in,
                              void* d_out, int out_size) {
    const float* Q = (const float*)d_in[0];
    const float* K = (const float*)d_in[1];
    const float* V = (const float*)d_in[2];
    const int* idxs = (const int*)d_in[3];
    float* out = (float*)d_out;

    // order: k_flash is user launch #4 (profiled).
    k_vmean<<<BH, 256>>>(V);                                  // 1
    k_M<<<(BH * Lq) / 8, 256>>>(Q, K, idxs);                  // 2
    k_topk<<<BH, 256>>>();                                    // 3
    k_flash<<<BH * NS, 256>>>(Q, K, V);                       // 4  <-- profiled
    k_fill<<<(BH * Lq * Dq / 4) / 256, 256>>>((float4*)out);  // 5
    k_comb<<<(BH * NT * Dq + 255) / 256, 256>>>(out);         // 6
}